// round 11
// baseline (speedup 1.0000x reference)
#include <cuda_runtime.h>
#include <cuda_fp16.h>
#include <cstdint>

#define Bdim   256
#define Hdim   1024
#define G4     4096
#define Tsteps 128
#define DO     128
#define NCH    8                     // 128-k tiles (g_hf / g_xA / g_B0 / g_Wp)
#define NCW    16                    // 64-k chunks (persist)
#define AT_EL  16384                 // 128 rows x 128 k halves (32 KB)
#define WT_EL  4096                  // 64 j-rows x 64 k halves (8 KB)

// ---------------- device scratch ------------------------------------------
__device__ __half g_B0[(size_t)G4 * Hdim];      // W_ih fp16, [nt32][c8][jl128][kin128]
__device__ __half g_Bc[(size_t)G4 * Hdim];      // (W_ih+W_hh) fp16, [nt64][c16][jl64][kin64]
__device__ __half g_xA[(size_t)Bdim * Hdim];    // x fp16, tiled (128-k)
__device__ __half g_hf[(size_t)Tsteps * Bdim * Hdim]; // h fp16, [t][rt][c8][rl][kin128]
__device__ __half g_Wp[(size_t)DO * Hdim];      // W_out fp16, [c8][d][kin128]
__device__ float g_c[(size_t)Bdim * Hdim];      // cell state (step0 -> persist handoff)
__device__ float g_bp[G4];                      // bias, j = hcol*4+gate
__device__ unsigned g_flag[2][64];              // distributed barrier flags

// ---------------- helpers ---------------------------------------------------
__device__ __forceinline__ uint32_t smem_u32(const void* p) {
    uint32_t a;
    asm("{ .reg .u64 t; cvta.to.shared.u64 t, %1; cvt.u32.u64 %0, t; }" : "=r"(a) : "l"(p));
    return a;
}
__device__ __forceinline__ float sigf(float v)   { return 1.0f / (1.0f + __expf(-v)); }
__device__ __forceinline__ float tanhf_(float v) { return 2.0f / (1.0f + __expf(-2.0f * v)) - 1.0f; }

__device__ __forceinline__ void cpasync16(uint32_t dst, const void* src) {
    asm volatile("cp.async.cg.shared.global [%0], [%1], 16;" :: "r"(dst), "l"(src) : "memory");
}
__device__ __forceinline__ void cp_commit() { asm volatile("cp.async.commit_group;" ::: "memory"); }

__device__ __forceinline__ void ldm_x4(uint32_t* r, uint32_t addr) {
    asm volatile("ldmatrix.sync.aligned.m8n8.x4.shared.b16 {%0,%1,%2,%3}, [%4];"
                 : "=r"(r[0]), "=r"(r[1]), "=r"(r[2]), "=r"(r[3]) : "r"(addr));
}
__device__ __forceinline__ void mma_f16(float* d, const uint32_t* a, uint32_t b0, uint32_t b1) {
    asm volatile(
        "mma.sync.aligned.m16n8k16.row.col.f32.f16.f16.f32 "
        "{%0,%1,%2,%3}, {%4,%5,%6,%7}, {%8,%9}, {%0,%1,%2,%3};"
        : "+f"(d[0]), "+f"(d[1]), "+f"(d[2]), "+f"(d[3])
        : "r"(a[0]), "r"(a[1]), "r"(a[2]), "r"(a[3]), "r"(b0), "r"(b1));
}
// ldmatrix lane address, 128B-row tile, per-8-row XOR swizzle
__device__ __forceinline__ uint32_t tile_addr(uint32_t base, int row0, int k0, int lane) {
    int g = lane >> 3;
    int r = row0 + (lane & 7) + ((g & 1) << 3);
    int kE = k0 + ((g >> 1) << 3);
    return base + r * 128 + ((kE * 2) ^ ((r & 7) << 4));
}
// ldmatrix lane address, 256B-row tile
__device__ __forceinline__ uint32_t tile_addr2(uint32_t base, int row0, int k0, int lane) {
    int g = lane >> 3;
    int r = row0 + (lane & 7) + ((g & 1) << 3);
    int kE = k0 + ((g >> 1) << 3);
    return base + r * 256 + ((kE * 2) ^ ((r & 7) << 4));
}

// distributed-flag barrier: 64 CTAs per mt group, generation = t
__device__ __forceinline__ void grid_bar(int mt, int cta, unsigned t) {
    __syncthreads();
    if (threadIdx.x == 0) {
        __threadfence();
        atomicExch(&g_flag[mt][cta], t);
    }
    if (threadIdx.x < 64) {
        while (atomicAdd(&g_flag[mt][threadIdx.x], 0u) < t) {}
        __threadfence();
    }
    __syncthreads();
}

// ---------------- pack kernel ----------------------------------------------
__global__ void pack_kernel(const float* __restrict__ Wih, const float* __restrict__ Whh,
                            const float* __restrict__ bih, const float* __restrict__ bhh,
                            const float* __restrict__ Wout, const float* __restrict__ x) {
    size_t idx = (size_t)blockIdx.x * 256 + threadIdx.x;   // 0 .. G4*Hdim-1
    {
        int j = (int)(idx >> 10), k = (int)(idx & 1023);
        int hcol = j >> 2, g = j & 3;
        size_t src = (size_t)(g * Hdim + hcol) * Hdim + k;
        float wi = Wih[src];
        size_t d0 = ((size_t)((j >> 7) * NCH + (k >> 7))) * AT_EL + (size_t)(j & 127) * 128 + (k & 127);
        g_B0[d0] = __float2half_rn(wi);
        size_t dc = ((size_t)((j >> 6) * NCW + (k >> 6))) * WT_EL + (size_t)(j & 63) * 64 + (k & 63);
        g_Bc[dc] = __float2half_rn(wi + Whh[src]);
    }
    if (idx < (size_t)Bdim * Hdim) {
        int r = (int)(idx >> 10), k = (int)(idx & 1023);
        size_t dst = ((size_t)((r >> 7) * NCH + (k >> 7))) * AT_EL + (size_t)(r & 127) * 128 + (k & 127);
        g_xA[dst] = __float2half_rn(x[idx]);
    }
    if (idx < G4) {
        int hcol = (int)idx >> 2, g = (int)idx & 3;
        g_bp[idx] = bih[g * Hdim + hcol] + bhh[g * Hdim + hcol];
    }
    if (idx < (size_t)Hdim * DO) {
        int k = (int)(idx >> 7), d = (int)(idx & (DO - 1));
        size_t dst = (size_t)(k >> 7) * AT_EL + (size_t)d * 128 + (k & 127);
        g_Wp[dst] = __float2half_rn(Wout[(size_t)d * Hdim + k]);
    }
    if (idx < 128)                          // reset barrier flags every launch
        ((unsigned*)g_flag)[idx] = 0u;
}

// ---------------- t = 0 step (streamed, 256 thr) -----------------------------
#define S0_STG 49152
#define S0_A   0
#define S0_B   16384
#define S0_SMEM (3 * S0_STG)

__global__ void __launch_bounds__(256, 1) lstm_step0_kernel() {
    extern __shared__ char smem[];
    const uint32_t sb = smem_u32(smem);
    const int tid = threadIdx.x;
    const int wid = tid >> 5, lane = tid & 31;
    const int nt = blockIdx.x, mt = blockIdx.y;
    const int rt = mt >> 1, rl0 = (mt & 1) * 64;

    const char* Aa = (const char*)(g_xA + (size_t)rt * NCH * AT_EL) + rl0 * 256;
    const char* Bp = (const char*)(g_B0 + (size_t)nt * NCH * AT_EL);

    auto issue = [&](int c) {
        if (c < NCH) {
            uint32_t stg = sb + (c % 3) * S0_STG;
            const char* pa = Aa + (size_t)c * AT_EL * 2;
            const char* pb = Bp + (size_t)c * AT_EL * 2;
            {
                int r = tid >> 2;
                #pragma unroll
                for (int p = 0; p < 4; p++) {
                    int kb = (tid & 3) * 16 + p * 64;
                    uint32_t sw = r * 256 + (kb ^ ((r & 7) << 4));
                    cpasync16(stg + S0_A + sw, pa + r * 256 + kb);
                }
            }
            {
                int r = tid >> 1;
                #pragma unroll
                for (int p = 0; p < 8; p++) {
                    int kb = (tid & 1) * 16 + p * 32;
                    uint32_t sw = r * 256 + (kb ^ ((r & 7) << 4));
                    cpasync16(stg + S0_B + sw, pb + r * 256 + kb);
                }
            }
        }
        cp_commit();
    };

    const int wr = wid >> 2, wc = wid & 3;
    const int mrow0 = wr * 32, n0 = wc * 32;

    float acc[2][4][4];
    #pragma unroll
    for (int mf = 0; mf < 2; mf++)
        #pragma unroll
        for (int nf = 0; nf < 4; nf++)
            #pragma unroll
            for (int q = 0; q < 4; q++) acc[mf][nf][q] = 0.0f;

    issue(0); issue(1);
    for (int c = 0; c < NCH; c++) {
        asm volatile("cp.async.wait_group 1;" ::: "memory");
        __syncthreads();
        uint32_t stg = sb + (c % 3) * S0_STG;

        uint32_t fa[2][2][4], fb[2][2][4];
        #pragma unroll
        for (int mf = 0; mf < 2; mf++)
            ldm_x4(fa[0][mf], tile_addr2(stg + S0_A, mrow0 + mf * 16, 0, lane));
        #pragma unroll
        for (int hf = 0; hf < 2; hf++)
            ldm_x4(fb[0][hf], tile_addr2(stg + S0_B, n0 + hf * 16, 0, lane));
        #pragma unroll
        for (int kst = 0; kst < 8; kst++) {
            const int cur = kst & 1, nxt = cur ^ 1;
            if (kst < 7) {
                const int k0 = (kst + 1) * 16;
                #pragma unroll
                for (int mf = 0; mf < 2; mf++)
                    ldm_x4(fa[nxt][mf], tile_addr2(stg + S0_A, mrow0 + mf * 16, k0, lane));
                #pragma unroll
                for (int hf = 0; hf < 2; hf++)
                    ldm_x4(fb[nxt][hf], tile_addr2(stg + S0_B, n0 + hf * 16, k0, lane));
            }
            #pragma unroll
            for (int mf = 0; mf < 2; mf++)
                #pragma unroll
                for (int nf = 0; nf < 4; nf++) {
                    const int hf = nf >> 1, lo = nf & 1;
                    mma_f16(acc[mf][nf], fa[cur][mf], fb[cur][hf][lo], fb[cur][hf][lo + 2]);
                }
        }
        issue(c + 2);
    }

    const int quad = lane >> 2, qp = lane & 3;
    const bool oddl = (lane & 1) != 0;
    const int mtb = mt * 64;

    #pragma unroll
    for (int mf = 0; mf < 2; mf++)
        #pragma unroll
        for (int nf = 0; nf < 4; nf++) {
            float* a = acc[mf][nf];
            int jb = nt * 128 + wc * 32 + nf * 8 + 2 * qp;
            float be = g_bp[jb], bo = g_bp[jb + 1];
            a[0] += be; a[1] += bo; a[2] += be; a[3] += bo;

            float p0 = __shfl_xor_sync(0xffffffffu, a[0], 1);
            float p1 = __shfl_xor_sync(0xffffffffu, a[1], 1);
            float p2 = __shfl_xor_sync(0xffffffffu, a[2], 1);
            float p3 = __shfl_xor_sync(0xffffffffu, a[3], 1);

            float vi = oddl ? p2 : a[0];
            float vf = oddl ? p3 : a[1];
            float vg = oddl ? a[2] : p0;
            float vo = oddl ? a[3] : p1;

            int row_g = mtb + wr * 32 + mf * 16 + quad + (oddl ? 8 : 0);
            int hc    = nt * 32 + wc * 8 + nf * 2 + (qp >> 1);

            float cn = sigf(vi) * tanhf_(vg);        // c0 = 0
            float hn = sigf(vo) * tanhf_(cn);
            g_c[(size_t)row_g * Hdim + hc] = cn;

            int rt2 = row_g >> 7, rl = row_g & 127;
            size_t hb = (((size_t)rt2 * NCH + (hc >> 7))) * AT_EL + (size_t)rl * 128 + (hc & 127);
            g_hf[hb] = __float2half_rn(hn);
        }
}

// ---------------- persistent kernel: steps 1..127, 512 threads ---------------
// 128 CTAs: nt = bid>>1 (64 gate cols), mt = bid&1 (128 rows).
// TWO independent sync groups per CTA (warps 0-7 / 8-15), each owning 32 gate
// cols and its own 3-stage 16KB A ring + named barrier. Shared: resident W.
// SMEM: [grp0 ring 48K][grp1 ring 48K][W 128K] = 224K.
#define PG_STG 16384
#define PG_RING 49152
#define P_OFF_W (2 * PG_RING)
#define P_SMEM  (P_OFF_W + 131072)      // 229376

__global__ void __launch_bounds__(512, 1) lstm_persist_kernel() {
    extern __shared__ char smem[];
    const uint32_t sb = smem_u32(smem);
    const int tid = threadIdx.x;
    const int wid = tid >> 5, lane = tid & 31;
    const int nt = blockIdx.x >> 1, mt = blockIdx.x & 1;
    const int grp = tid >> 8;            // sync group 0/1
    const int gtid = tid & 255;
    const uint32_t sbW = sb + P_OFF_W;
    const uint32_t sbG = sb + grp * PG_RING;

    // resident W: 16 chunk-tiles (64 j-rows x 64 k = 8 KB each) = 128 KB
    {
        const char* wbase = (const char*)(g_Bc + (size_t)nt * NCW * WT_EL);
        for (int c = 0; c < NCW; c++) {
            const char* src = wbase + (size_t)c * WT_EL * 2;
            int r = tid >> 3;             // 0..63
            int kb = (tid & 7) * 16;      // 0..112
            uint32_t sw = r * 128 + (kb ^ ((r & 7) << 4));
            cpasync16(sbW + c * 8192 + sw, src + r * 128 + kb);
        }
        cp_commit();
        asm volatile("cp.async.wait_group 0;" ::: "memory");
        __syncthreads();
    }

    const int widg = wid & 7;
    const int wr = widg >> 1, wc = widg & 1;   // 4 row groups x 2 col groups
    const int mrow0 = wr * 32;
    const int wn0 = grp * 32 + wc * 16;        // j-row in W chunk tile
    const int quad = lane >> 2, qp = lane & 3;
    const bool oddl = (lane & 1) != 0;

    int rows[2], hcs[2];
    #pragma unroll
    for (int mf = 0; mf < 2; mf++)
        rows[mf] = mt * 128 + wr * 32 + mf * 16 + quad + (oddl ? 8 : 0);
    #pragma unroll
    for (int nf = 0; nf < 2; nf++)
        hcs[nf] = nt * 16 + grp * 8 + wc * 4 + nf * 2 + (qp >> 1);

    float bias0[2], bias1[2], c_reg[2][2];
    #pragma unroll
    for (int nf = 0; nf < 2; nf++) {
        int jb = nt * 64 + grp * 32 + wc * 16 + nf * 8 + 2 * qp;
        bias0[nf] = g_bp[jb];
        bias1[nf] = g_bp[jb + 1];
        #pragma unroll
        for (int mf = 0; mf < 2; mf++)
            c_reg[mf][nf] = g_c[(size_t)rows[mf] * Hdim + hcs[nf]];
    }

    for (int t = 1; t < Tsteps; t++) {
        const char* Aa = (const char*)(g_hf + ((size_t)(t - 1) * 2 + mt) * (NCH * AT_EL));

        // per-group A loader: 64-k chunk = 128 rows x 128 B (half of a 128-k tile)
        auto issue = [&](int c) {
            if (c < NCW) {
                uint32_t stg = sbG + (c % 3) * PG_STG;
                const char* pa = Aa + (size_t)(c >> 1) * AT_EL * 2 + (c & 1) * 128;
                int r = gtid >> 1;        // 0..127
                #pragma unroll
                for (int p = 0; p < 4; p++) {
                    int kb = (gtid & 1) * 16 + p * 32;
                    uint32_t sw = r * 128 + (kb ^ ((r & 7) << 4));
                    cpasync16(stg + sw, pa + r * 256 + kb);
                }
            }
            cp_commit();
        };

        float acc[2][2][4];
        #pragma unroll
        for (int mf = 0; mf < 2; mf++)
            #pragma unroll
            for (int nf = 0; nf < 2; nf++)
                #pragma unroll
                for (int q = 0; q < 4; q++) acc[mf][nf][q] = 0.0f;

        issue(0); issue(1);
        for (int c = 0; c < NCW; c++) {
            asm volatile("cp.async.wait_group 1;" ::: "memory");
            asm volatile("bar.sync %0, %1;" :: "r"(grp + 1), "r"(256) : "memory");
            uint32_t stg = sbG + (c % 3) * PG_STG;
            uint32_t wch = sbW + c * 8192;

            uint32_t fa[2][2][4], fw[2][4];
            #pragma unroll
            for (int mf = 0; mf < 2; mf++)
                ldm_x4(fa[0][mf], tile_addr(stg, mrow0 + mf * 16, 0, lane));
            ldm_x4(fw[0], tile_addr(wch, wn0, 0, lane));

            #pragma unroll
            for (int kst = 0; kst < 4; kst++) {
                const int cur = kst & 1, nxt = cur ^ 1;
                if (kst < 3) {
                    const int k0 = (kst + 1) * 16;
                    #pragma unroll
                    for (int mf = 0; mf < 2; mf++)
                        ldm_x4(fa[nxt][mf], tile_addr(stg, mrow0 + mf * 16, k0, lane));
                    ldm_x4(fw[nxt], tile_addr(wch, wn0, k0, lane));
                }
                #pragma unroll
                for (int mf = 0; mf < 2; mf++)
                    #pragma unroll
                    for (int nf = 0; nf < 2; nf++)
                        mma_f16(acc[mf][nf], fa[cur][mf], fw[cur][nf], fw[cur][nf + 2]);
            }
            // stage consumed only after next group barrier; safe to re-issue now
            asm volatile("bar.sync %0, %1;" :: "r"(grp + 1), "r"(256) : "memory");
            issue(c + 2);
        }

        // ---- LSTM cell epilogue (all 16 warps, own gates) ----
        #pragma unroll
        for (int mf = 0; mf < 2; mf++)
            #pragma unroll
            for (int nf = 0; nf < 2; nf++) {
                float* a = acc[mf][nf];
                a[0] += bias0[nf]; a[1] += bias1[nf];
                a[2] += bias0[nf]; a[3] += bias1[nf];

                float p0 = __shfl_xor_sync(0xffffffffu, a[0], 1);
                float p1 = __shfl_xor_sync(0xffffffffu, a[1], 1);
                float p2 = __shfl_xor_sync(0xffffffffu, a[2], 1);
                float p3 = __shfl_xor_sync(0xffffffffu, a[3], 1);

                float vi = oddl ? p2 : a[0];
                float vf = oddl ? p3 : a[1];
                float vg = oddl ? a[2] : p0;
                float vo = oddl ? a[3] : p1;

                float cn = sigf(vf) * c_reg[mf][nf] + sigf(vi) * tanhf_(vg);
                float hn = sigf(vo) * tanhf_(cn);
                c_reg[mf][nf] = cn;

                int row_g = rows[mf], hc = hcs[nf];
                int rl = row_g & 127;
                size_t hb = (((size_t)t * 2 + mt) * NCH + (hc >> 7)) * AT_EL
                          + (size_t)rl * 128 + (hc & 127);
                g_hf[hb] = __float2half_rn(hn);
            }

        if (t < Tsteps - 1) grid_bar(mt, nt, (unsigned)t);
    }
}

// ---------------- projection (fp16 HMMA) -------------------------------------
#define PJ_STG 65536
#define PJ_A   0
#define PJ_B   32768
#define PJ_SMEM (3 * PJ_STG)

__global__ void __launch_bounds__(512, 1) proj_kernel(const float* __restrict__ bout,
                                                      float* __restrict__ out) {
    extern __shared__ char smem[];
    const uint32_t sb = smem_u32(smem);
    const int tid = threadIdx.x;
    const int wid = tid >> 5, lane = tid & 31;
    const int t = blockIdx.x >> 1, rt = blockIdx.x & 1;

    const char* Aa = (const char*)(g_hf + ((size_t)t * 2 + rt) * (NCH * AT_EL));

    auto issue = [&](int c) {
        if (c < NCH) {
            uint32_t stg = sb + (c % 3) * PJ_STG;
            const char* pa = Aa + (size_t)c * AT_EL * 2;
            const char* pb = (const char*)(g_Wp + (size_t)c * AT_EL);
            int r = tid >> 2;
            #pragma unroll
            for (int p = 0; p < 4; p++) {
                int kb = (tid & 3) * 16 + p * 64;
                uint32_t sw = r * 256 + (kb ^ ((r & 7) << 4));
                cpasync16(stg + PJ_A + sw, pa + r * 256 + kb);
                cpasync16(stg + PJ_B + sw, pb + r * 256 + kb);
            }
        }
        cp_commit();
    };

    const int wr = wid >> 2, wc = wid & 3;
    const int mrow0 = wr * 32, n0 = wc * 32;

    float acc[2][4][4];
    #pragma unroll
    for (int mf = 0; mf < 2; mf++)
        #pragma unroll
        for (int nf = 0; nf < 4; nf++)
            #pragma unroll
            for (int q = 0; q < 4; q++) acc[mf][nf][q] = 0.0f;

    issue(0); issue(1);
    for (int c = 0; c < NCH; c++) {
        asm volatile("cp.async.wait_group 1;" ::: "memory");
        __syncthreads();
        uint32_t stg = sb + (c % 3) * PJ_STG;

        uint32_t fa[2][2][4], fb[2][2][4];
        #pragma unroll
        for (int mf = 0; mf < 2; mf++)
            ldm_x4(fa[0][mf], tile_addr2(stg + PJ_A, mrow0 + mf * 16, 0, lane));
        #pragma unroll
        for (int hf = 0; hf < 2; hf++)
            ldm_x4(fb[0][hf], tile_addr2(stg + PJ_B, n0 + hf * 16, 0, lane));
        #pragma unroll
        for (int kst = 0; kst < 8; kst++) {
            const int cur = kst & 1, nxt = cur ^ 1;
            if (kst < 7) {
                const int k0 = (kst + 1) * 16;
                #pragma unroll
                for (int mf = 0; mf < 2; mf++)
                    ldm_x4(fa[nxt][mf], tile_addr2(stg + PJ_A, mrow0 + mf * 16, k0, lane));
                #pragma unroll
                for (int hf = 0; hf < 2; hf++)
                    ldm_x4(fb[nxt][hf], tile_addr2(stg + PJ_B, n0 + hf * 16, k0, lane));
            }
            #pragma unroll
            for (int mf = 0; mf < 2; mf++)
                #pragma unroll
                for (int nf = 0; nf < 4; nf++) {
                    const int hf = nf >> 1, lo = nf & 1;
                    mma_f16(acc[mf][nf], fa[cur][mf], fb[cur][hf][lo], fb[cur][hf][lo + 2]);
                }
        }
        issue(c + 2);
    }

    const int quad = lane >> 2, qp = lane & 3;
    #pragma unroll
    for (int mf = 0; mf < 2; mf++)
        #pragma unroll
        for (int nf = 0; nf < 4; nf++) {
            float* a = acc[mf][nf];
            int col = wc * 32 + nf * 8 + 2 * qp;
            float be = bout[col], bo = bout[col + 1];
            int row0 = wr * 32 + mf * 16 + quad;
            int b0 = rt * 128 + row0;
            float2 v0 = make_float2(a[0] + be, a[1] + bo);
            float2 v1 = make_float2(a[2] + be, a[3] + bo);
            *(float2*)&out[((size_t)b0 * Tsteps + t) * DO + col] = v0;
            *(float2*)&out[((size_t)(b0 + 8) * Tsteps + t) * DO + col] = v1;
        }
}

// ---------------- launcher ---------------------------------------------------
extern "C" void kernel_launch(void* const* d_in, const int* in_sizes, int n_in,
                              void* d_out, int out_size) {
    const float* x    = (const float*)d_in[0];
    const float* Wih  = (const float*)d_in[1];
    const float* Whh  = (const float*)d_in[2];
    const float* bih  = (const float*)d_in[3];
    const float* bhh  = (const float*)d_in[4];
    const float* Wout = (const float*)d_in[5];
    const float* bout = (const float*)d_in[6];
    float* out = (float*)d_out;

    cudaFuncSetAttribute(lstm_step0_kernel, cudaFuncAttributeMaxDynamicSharedMemorySize, S0_SMEM);
    cudaFuncSetAttribute(lstm_persist_kernel, cudaFuncAttributeMaxDynamicSharedMemorySize, P_SMEM);
    cudaFuncSetAttribute(proj_kernel, cudaFuncAttributeMaxDynamicSharedMemorySize, PJ_SMEM);

    pack_kernel<<<(G4 * Hdim) / 256, 256>>>(Wih, Whh, bih, bhh, Wout, x);
    lstm_step0_kernel<<<dim3(32, 4), 256, S0_SMEM>>>();
    lstm_persist_kernel<<<128, 512, P_SMEM>>>();
    proj_kernel<<<256, 512, PJ_SMEM>>>(bout, out);
}

// round 12
// speedup vs baseline: 1.3106x; 1.3106x over previous
#include <cuda_runtime.h>
#include <cuda_fp16.h>
#include <cstdint>

#define Bdim   256
#define Hdim   1024
#define G4     4096
#define Tsteps 128
#define DO     128
#define NCH    8                     // 128-k chunks
#define AT_EL  16384                 // 128 rows x 128 k halves (32 KB)
#define WT_EL  8192                  // 64 j-rows x 128 k halves (16 KB)

// ---------------- device scratch ------------------------------------------
__device__ __half g_B0[(size_t)G4 * Hdim];      // W_ih fp16, [nt32][c8][jl128][kin128]
__device__ __half g_Bc[(size_t)G4 * Hdim];      // (W_ih+W_hh) fp16, [ct64][c8][jl64][kin128]
__device__ __half g_xA[(size_t)Bdim * Hdim];    // x fp16, tiled (128-k)
__device__ __half g_hf[(size_t)Tsteps * Bdim * Hdim]; // h fp16, [t][rt][c8][rl][kin128]
__device__ __half g_Wp[(size_t)DO * Hdim];      // W_out fp16, [c8][d][kin128]
__device__ float g_c[(size_t)Bdim * Hdim];      // cell state (step0 -> persist handoff)
__device__ float g_bp[G4];                      // bias, j = hcol*4+gate
__device__ unsigned g_flag[4][64];              // distributed barrier flags (4 row groups)

// ---------------- helpers ---------------------------------------------------
__device__ __forceinline__ uint32_t smem_u32(const void* p) {
    uint32_t a;
    asm("{ .reg .u64 t; cvta.to.shared.u64 t, %1; cvt.u32.u64 %0, t; }" : "=r"(a) : "l"(p));
    return a;
}
__device__ __forceinline__ float sigf(float v)   { return 1.0f / (1.0f + __expf(-v)); }
__device__ __forceinline__ float tanhf_(float v) { return 2.0f / (1.0f + __expf(-2.0f * v)) - 1.0f; }

__device__ __forceinline__ void cpasync16(uint32_t dst, const void* src) {
    asm volatile("cp.async.cg.shared.global [%0], [%1], 16;" :: "r"(dst), "l"(src) : "memory");
}
__device__ __forceinline__ void cp_commit() { asm volatile("cp.async.commit_group;" ::: "memory"); }

__device__ __forceinline__ void ldm_x4(uint32_t* r, uint32_t addr) {
    asm volatile("ldmatrix.sync.aligned.m8n8.x4.shared.b16 {%0,%1,%2,%3}, [%4];"
                 : "=r"(r[0]), "=r"(r[1]), "=r"(r[2]), "=r"(r[3]) : "r"(addr));
}
__device__ __forceinline__ void mma_f16(float* d, const uint32_t* a, uint32_t b0, uint32_t b1) {
    asm volatile(
        "mma.sync.aligned.m16n8k16.row.col.f32.f16.f16.f32 "
        "{%0,%1,%2,%3}, {%4,%5,%6,%7}, {%8,%9}, {%0,%1,%2,%3};"
        : "+f"(d[0]), "+f"(d[1]), "+f"(d[2]), "+f"(d[3])
        : "r"(a[0]), "r"(a[1]), "r"(a[2]), "r"(a[3]), "r"(b0), "r"(b1));
}
// ldmatrix lane address, 256B-row tile, per-8-row XOR swizzle
__device__ __forceinline__ uint32_t tile_addr2(uint32_t base, int row0, int k0, int lane) {
    int g = lane >> 3;
    int r = row0 + (lane & 7) + ((g & 1) << 3);
    int kE = k0 + ((g >> 1) << 3);
    return base + r * 256 + ((kE * 2) ^ ((r & 7) << 4));
}

// distributed-flag barrier: 4 row groups x 64 CTAs, generation = t
__device__ __forceinline__ void grid_bar(int g, int cta, unsigned t) {
    __syncthreads();
    if (threadIdx.x == 0) {
        __threadfence();
        atomicExch(&g_flag[g][cta], t);
    }
    if (threadIdx.x < 64) {
        while (atomicAdd(&g_flag[g][threadIdx.x], 0u) < t) {}
        __threadfence();
    }
    __syncthreads();
}

// ---------------- pack kernel ----------------------------------------------
__global__ void pack_kernel(const float* __restrict__ Wih, const float* __restrict__ Whh,
                            const float* __restrict__ bih, const float* __restrict__ bhh,
                            const float* __restrict__ Wout, const float* __restrict__ x) {
    size_t idx = (size_t)blockIdx.x * 256 + threadIdx.x;   // 0 .. G4*Hdim-1
    {
        int j = (int)(idx >> 10), k = (int)(idx & 1023);
        int hcol = j >> 2, g = j & 3;
        size_t src = (size_t)(g * Hdim + hcol) * Hdim + k;
        float wi = Wih[src];
        size_t d0 = ((size_t)((j >> 7) * NCH + (k >> 7))) * AT_EL + (size_t)(j & 127) * 128 + (k & 127);
        g_B0[d0] = __float2half_rn(wi);
        size_t dc = ((size_t)((j >> 6) * NCH + (k >> 7))) * WT_EL + (size_t)(j & 63) * 128 + (k & 127);
        g_Bc[dc] = __float2half_rn(wi + Whh[src]);
    }
    if (idx < (size_t)Bdim * Hdim) {
        int r = (int)(idx >> 10), k = (int)(idx & 1023);
        size_t dst = ((size_t)((r >> 7) * NCH + (k >> 7))) * AT_EL + (size_t)(r & 127) * 128 + (k & 127);
        g_xA[dst] = __float2half_rn(x[idx]);
    }
    if (idx < G4) {
        int hcol = (int)idx >> 2, g = (int)idx & 3;
        g_bp[idx] = bih[g * Hdim + hcol] + bhh[g * Hdim + hcol];
    }
    if (idx < (size_t)Hdim * DO) {
        int k = (int)(idx >> 7), d = (int)(idx & (DO - 1));
        size_t dst = (size_t)(k >> 7) * AT_EL + (size_t)d * 128 + (k & 127);
        g_Wp[dst] = __float2half_rn(Wout[(size_t)d * Hdim + k]);
    }
    if (idx < 256)                          // reset barrier flags every launch
        ((unsigned*)g_flag)[idx] = 0u;
}

// ---------------- t = 0 step (streamed, 256 thr) -----------------------------
#define S0_STG 49152
#define S0_A   0
#define S0_B   16384
#define S0_SMEM (3 * S0_STG)

__global__ void __launch_bounds__(256, 1) lstm_step0_kernel() {
    extern __shared__ char smem[];
    const uint32_t sb = smem_u32(smem);
    const int tid = threadIdx.x;
    const int wid = tid >> 5, lane = tid & 31;
    const int nt = blockIdx.x, mt = blockIdx.y;
    const int rt = mt >> 1, rl0 = (mt & 1) * 64;

    const char* Aa = (const char*)(g_xA + (size_t)rt * NCH * AT_EL) + rl0 * 256;
    const char* Bp = (const char*)(g_B0 + (size_t)nt * NCH * AT_EL);

    auto issue = [&](int c) {
        if (c < NCH) {
            uint32_t stg = sb + (c % 3) * S0_STG;
            const char* pa = Aa + (size_t)c * AT_EL * 2;
            const char* pb = Bp + (size_t)c * AT_EL * 2;
            {
                int r = tid >> 2;
                #pragma unroll
                for (int p = 0; p < 4; p++) {
                    int kb = (tid & 3) * 16 + p * 64;
                    uint32_t sw = r * 256 + (kb ^ ((r & 7) << 4));
                    cpasync16(stg + S0_A + sw, pa + r * 256 + kb);
                }
            }
            {
                int r = tid >> 1;
                #pragma unroll
                for (int p = 0; p < 8; p++) {
                    int kb = (tid & 1) * 16 + p * 32;
                    uint32_t sw = r * 256 + (kb ^ ((r & 7) << 4));
                    cpasync16(stg + S0_B + sw, pb + r * 256 + kb);
                }
            }
        }
        cp_commit();
    };

    const int wr = wid >> 2, wc = wid & 3;
    const int mrow0 = wr * 32, n0 = wc * 32;

    float acc[2][4][4];
    #pragma unroll
    for (int mf = 0; mf < 2; mf++)
        #pragma unroll
        for (int nf = 0; nf < 4; nf++)
            #pragma unroll
            for (int q = 0; q < 4; q++) acc[mf][nf][q] = 0.0f;

    issue(0); issue(1);
    for (int c = 0; c < NCH; c++) {
        asm volatile("cp.async.wait_group 1;" ::: "memory");
        __syncthreads();
        uint32_t stg = sb + (c % 3) * S0_STG;

        uint32_t fa[2][2][4], fb[2][2][4];
        #pragma unroll
        for (int mf = 0; mf < 2; mf++)
            ldm_x4(fa[0][mf], tile_addr2(stg + S0_A, mrow0 + mf * 16, 0, lane));
        #pragma unroll
        for (int hf = 0; hf < 2; hf++)
            ldm_x4(fb[0][hf], tile_addr2(stg + S0_B, n0 + hf * 16, 0, lane));
        #pragma unroll
        for (int kst = 0; kst < 8; kst++) {
            const int cur = kst & 1, nxt = cur ^ 1;
            if (kst < 7) {
                const int k0 = (kst + 1) * 16;
                #pragma unroll
                for (int mf = 0; mf < 2; mf++)
                    ldm_x4(fa[nxt][mf], tile_addr2(stg + S0_A, mrow0 + mf * 16, k0, lane));
                #pragma unroll
                for (int hf = 0; hf < 2; hf++)
                    ldm_x4(fb[nxt][hf], tile_addr2(stg + S0_B, n0 + hf * 16, k0, lane));
            }
            #pragma unroll
            for (int mf = 0; mf < 2; mf++)
                #pragma unroll
                for (int nf = 0; nf < 4; nf++) {
                    const int hf = nf >> 1, lo = nf & 1;
                    mma_f16(acc[mf][nf], fa[cur][mf], fb[cur][hf][lo], fb[cur][hf][lo + 2]);
                }
        }
        issue(c + 2);
    }

    const int quad = lane >> 2, qp = lane & 3;
    const bool oddl = (lane & 1) != 0;
    const int mtb = mt * 64;

    #pragma unroll
    for (int mf = 0; mf < 2; mf++)
        #pragma unroll
        for (int nf = 0; nf < 4; nf++) {
            float* a = acc[mf][nf];
            int jb = nt * 128 + wc * 32 + nf * 8 + 2 * qp;
            float be = g_bp[jb], bo = g_bp[jb + 1];
            a[0] += be; a[1] += bo; a[2] += be; a[3] += bo;

            float p0 = __shfl_xor_sync(0xffffffffu, a[0], 1);
            float p1 = __shfl_xor_sync(0xffffffffu, a[1], 1);
            float p2 = __shfl_xor_sync(0xffffffffu, a[2], 1);
            float p3 = __shfl_xor_sync(0xffffffffu, a[3], 1);

            float vi = oddl ? p2 : a[0];
            float vf = oddl ? p3 : a[1];
            float vg = oddl ? a[2] : p0;
            float vo = oddl ? a[3] : p1;

            int row_g = mtb + wr * 32 + mf * 16 + quad + (oddl ? 8 : 0);
            int hc    = nt * 32 + wc * 8 + nf * 2 + (qp >> 1);

            float cn = sigf(vi) * tanhf_(vg);        // c0 = 0
            float hn = sigf(vo) * tanhf_(cn);
            g_c[(size_t)row_g * Hdim + hc] = cn;

            int rt2 = row_g >> 7, rl = row_g & 127;
            size_t hb = (((size_t)rt2 * NCH + (hc >> 7))) * AT_EL + (size_t)rl * 128 + (hc & 127);
            g_hf[hb] = __float2half_rn(hn);
        }
}

// ---------------- persistent kernel: steps 1..127 ----------------------------
// 256 CTAs (2/SM), 256 threads each. CTA tile: 64 rows x 64 gate cols.
// bid = ct*4 + rt4: rt4 = row tile (64 rows), ct = gate-col tile (64 cols).
// 8 warps: 2(row32) x 2(col32) x 2(k-half). Streams A and W, 3-stage ring.
// SMEM/CTA: 3 x (A 16K + W 16K) = 96K -> 192K/SM for 2 CTAs.
#define PP_STG 32768
#define PP_A   0
#define PP_W   16384
#define PP_SMEM (3 * PP_STG)

__global__ void __launch_bounds__(256, 2) lstm_persist_kernel() {
    extern __shared__ char smem[];
    const uint32_t sb = smem_u32(smem);
    const int tid = threadIdx.x;
    const int wid = tid >> 5, lane = tid & 31;
    const int rt4 = blockIdx.x & 3, ct = blockIdx.x >> 2;
    const int rl0 = (rt4 & 1) * 64;          // row offset within 128-row h tile
    const int rtH = rt4 >> 1;                // 128-row h tile index

    const int ks = wid >> 2, widL = wid & 3;
    const int wr = widL >> 1, wc = widL & 1;
    const int mrow0 = wr * 32, n0 = wc * 32;
    const int kb0 = ks * 64;
    const int quad = lane >> 2, qp = lane & 3;
    const bool oddl = (lane & 1) != 0;
    const int sidx = widL * 32 + lane;       // 0..127 scratch slot

    const char* Wb = (const char*)(g_Bc + (size_t)ct * NCH * WT_EL);

    int rows[2], hcs[4];
    #pragma unroll
    for (int mf = 0; mf < 2; mf++)
        rows[mf] = rt4 * 64 + wr * 32 + mf * 16 + quad + (oddl ? 8 : 0);
    #pragma unroll
    for (int nf = 0; nf < 4; nf++)
        hcs[nf] = ct * 16 + wc * 8 + nf * 2 + (qp >> 1);

    float bias0[4] = {0, 0, 0, 0}, bias1[4] = {0, 0, 0, 0}, c_reg[2][4];
    if (ks == 0) {
        #pragma unroll
        for (int nf = 0; nf < 4; nf++) {
            int jb = ct * 64 + wc * 32 + nf * 8 + 2 * qp;
            bias0[nf] = g_bp[jb];
            bias1[nf] = g_bp[jb + 1];
            #pragma unroll
            for (int mf = 0; mf < 2; mf++)
                c_reg[mf][nf] = g_c[(size_t)rows[mf] * Hdim + hcs[nf]];
        }
    }

    float4* scr4 = (float4*)smem;            // stage-0 area reused as scratch

    for (int t = 1; t < Tsteps; t++) {
        const char* Aa = (const char*)(g_hf + ((size_t)(t - 1) * 2 + rtH) * (NCH * AT_EL));

        auto issue = [&](int c) {
            if (c < NCH) {
                uint32_t stg = sb + (c % 3) * PP_STG;
                const char* pa = Aa + (size_t)c * AT_EL * 2 + (size_t)rl0 * 256;
                const char* pw = Wb + (size_t)c * WT_EL * 2;
                int r = tid >> 2;            // 0..63
                #pragma unroll
                for (int p = 0; p < 4; p++) {
                    int kb = (tid & 3) * 16 + p * 64;
                    uint32_t sw = r * 256 + (kb ^ ((r & 7) << 4));
                    cpasync16(stg + PP_A + sw, pa + r * 256 + kb);
                    cpasync16(stg + PP_W + sw, pw + r * 256 + kb);
                }
            }
            cp_commit();
        };

        float acc[2][4][4];
        #pragma unroll
        for (int mf = 0; mf < 2; mf++)
            #pragma unroll
            for (int nf = 0; nf < 4; nf++)
                #pragma unroll
                for (int q = 0; q < 4; q++) acc[mf][nf][q] = 0.0f;

        issue(0); issue(1);
        for (int c = 0; c < NCH; c++) {
            asm volatile("cp.async.wait_group 1;" ::: "memory");
            __syncthreads();
            uint32_t stg = sb + (c % 3) * PP_STG;

            uint32_t fa[2][2][4], fw[2][2][4];
            #pragma unroll
            for (int mf = 0; mf < 2; mf++)
                ldm_x4(fa[0][mf], tile_addr2(stg + PP_A, mrow0 + mf * 16, kb0, lane));
            #pragma unroll
            for (int hf = 0; hf < 2; hf++)
                ldm_x4(fw[0][hf], tile_addr2(stg + PP_W, n0 + hf * 16, kb0, lane));

            #pragma unroll
            for (int kst = 0; kst < 4; kst++) {
                const int cur = kst & 1, nxt = cur ^ 1;
                if (kst < 3) {
                    const int k0 = kb0 + (kst + 1) * 16;
                    #pragma unroll
                    for (int mf = 0; mf < 2; mf++)
                        ldm_x4(fa[nxt][mf], tile_addr2(stg + PP_A, mrow0 + mf * 16, k0, lane));
                    #pragma unroll
                    for (int hf = 0; hf < 2; hf++)
                        ldm_x4(fw[nxt][hf], tile_addr2(stg + PP_W, n0 + hf * 16, k0, lane));
                }
                #pragma unroll
                for (int mf = 0; mf < 2; mf++)
                    #pragma unroll
                    for (int nf = 0; nf < 4; nf++) {
                        const int hf = nf >> 1, lo = nf & 1;
                        mma_f16(acc[mf][nf], fa[cur][mf], fw[cur][hf][lo], fw[cur][hf][lo + 2]);
                    }
            }
            issue(c + 2);
        }

        // ---- k-half reduction via smem scratch (stage 0 free: chunk 6 consumed) ----
        if (ks == 1) {
            #pragma unroll
            for (int mf = 0; mf < 2; mf++)
                #pragma unroll
                for (int nf = 0; nf < 4; nf++)
                    scr4[(mf * 4 + nf) * 128 + sidx] =
                        make_float4(acc[mf][nf][0], acc[mf][nf][1], acc[mf][nf][2], acc[mf][nf][3]);
        }
        __syncthreads();

        // ---- LSTM cell epilogue (k-half 0 warps) ----
        if (ks == 0) {
            #pragma unroll
            for (int mf = 0; mf < 2; mf++)
                #pragma unroll
                for (int nf = 0; nf < 4; nf++) {
                    float* a = acc[mf][nf];
                    float4 rd = scr4[(mf * 4 + nf) * 128 + sidx];
                    a[0] += rd.x + bias0[nf];
                    a[1] += rd.y + bias1[nf];
                    a[2] += rd.z + bias0[nf];
                    a[3] += rd.w + bias1[nf];

                    float p0 = __shfl_xor_sync(0xffffffffu, a[0], 1);
                    float p1 = __shfl_xor_sync(0xffffffffu, a[1], 1);
                    float p2 = __shfl_xor_sync(0xffffffffu, a[2], 1);
                    float p3 = __shfl_xor_sync(0xffffffffu, a[3], 1);

                    float vi = oddl ? p2 : a[0];
                    float vf = oddl ? p3 : a[1];
                    float vg = oddl ? a[2] : p0;
                    float vo = oddl ? a[3] : p1;

                    float cn = sigf(vf) * c_reg[mf][nf] + sigf(vi) * tanhf_(vg);
                    float hn = sigf(vo) * tanhf_(cn);
                    c_reg[mf][nf] = cn;

                    int row_g = rows[mf], hc = hcs[nf];
                    int rl = row_g & 127;
                    size_t hb = (((size_t)t * 2 + (row_g >> 7)) * NCH + (hc >> 7)) * AT_EL
                              + (size_t)rl * 128 + (hc & 127);
                    g_hf[hb] = __float2half_rn(hn);
                }
        }

        if (t < Tsteps - 1) grid_bar(rt4, ct, (unsigned)t);
    }
}

// ---------------- projection (fp16 HMMA) -------------------------------------
#define PJ_STG 65536
#define PJ_A   0
#define PJ_B   32768
#define PJ_SMEM (3 * PJ_STG)

__global__ void __launch_bounds__(512, 1) proj_kernel(const float* __restrict__ bout,
                                                      float* __restrict__ out) {
    extern __shared__ char smem[];
    const uint32_t sb = smem_u32(smem);
    const int tid = threadIdx.x;
    const int wid = tid >> 5, lane = tid & 31;
    const int t = blockIdx.x >> 1, rt = blockIdx.x & 1;

    const char* Aa = (const char*)(g_hf + ((size_t)t * 2 + rt) * (NCH * AT_EL));

    auto issue = [&](int c) {
        if (c < NCH) {
            uint32_t stg = sb + (c % 3) * PJ_STG;
            const char* pa = Aa + (size_t)c * AT_EL * 2;
            const char* pb = (const char*)(g_Wp + (size_t)c * AT_EL);
            int r = tid >> 2;
            #pragma unroll
            for (int p = 0; p < 4; p++) {
                int kb = (tid & 3) * 16 + p * 64;
                uint32_t sw = r * 256 + (kb ^ ((r & 7) << 4));
                cpasync16(stg + PJ_A + sw, pa + r * 256 + kb);
                cpasync16(stg + PJ_B + sw, pb + r * 256 + kb);
            }
        }
        cp_commit();
    };

    const int wr = wid >> 2, wc = wid & 3;
    const int mrow0 = wr * 32, n0 = wc * 32;

    float acc[2][4][4];
    #pragma unroll
    for (int mf = 0; mf < 2; mf++)
        #pragma unroll
        for (int nf = 0; nf < 4; nf++)
            #pragma unroll
            for (int q = 0; q < 4; q++) acc[mf][nf][q] = 0.0f;

    issue(0); issue(1);
    for (int c = 0; c < NCH; c++) {
        asm volatile("cp.async.wait_group 1;" ::: "memory");
        __syncthreads();
        uint32_t stg = sb + (c % 3) * PJ_STG;

        uint32_t fa[2][2][4], fb[2][2][4];
        #pragma unroll
        for (int mf = 0; mf < 2; mf++)
            ldm_x4(fa[0][mf], tile_addr2(stg + PJ_A, mrow0 + mf * 16, 0, lane));
        #pragma unroll
        for (int hf = 0; hf < 2; hf++)
            ldm_x4(fb[0][hf], tile_addr2(stg + PJ_B, n0 + hf * 16, 0, lane));
        #pragma unroll
        for (int kst = 0; kst < 8; kst++) {
            const int cur = kst & 1, nxt = cur ^ 1;
            if (kst < 7) {
                const int k0 = (kst + 1) * 16;
                #pragma unroll
                for (int mf = 0; mf < 2; mf++)
                    ldm_x4(fa[nxt][mf], tile_addr2(stg + PJ_A, mrow0 + mf * 16, k0, lane));
                #pragma unroll
                for (int hf = 0; hf < 2; hf++)
                    ldm_x4(fb[nxt][hf], tile_addr2(stg + PJ_B, n0 + hf * 16, k0, lane));
            }
            #pragma unroll
            for (int mf = 0; mf < 2; mf++)
                #pragma unroll
                for (int nf = 0; nf < 4; nf++) {
                    const int hf = nf >> 1, lo = nf & 1;
                    mma_f16(acc[mf][nf], fa[cur][mf], fb[cur][hf][lo], fb[cur][hf][lo + 2]);
                }
        }
        issue(c + 2);
    }

    const int quad = lane >> 2, qp = lane & 3;
    #pragma unroll
    for (int mf = 0; mf < 2; mf++)
        #pragma unroll
        for (int nf = 0; nf < 4; nf++) {
            float* a = acc[mf][nf];
            int col = wc * 32 + nf * 8 + 2 * qp;
            float be = bout[col], bo = bout[col + 1];
            int row0 = wr * 32 + mf * 16 + quad;
            int b0 = rt * 128 + row0;
            float2 v0 = make_float2(a[0] + be, a[1] + bo);
            float2 v1 = make_float2(a[2] + be, a[3] + bo);
            *(float2*)&out[((size_t)b0 * Tsteps + t) * DO + col] = v0;
            *(float2*)&out[((size_t)(b0 + 8) * Tsteps + t) * DO + col] = v1;
        }
}

// ---------------- launcher ---------------------------------------------------
extern "C" void kernel_launch(void* const* d_in, const int* in_sizes, int n_in,
                              void* d_out, int out_size) {
    const float* x    = (const float*)d_in[0];
    const float* Wih  = (const float*)d_in[1];
    const float* Whh  = (const float*)d_in[2];
    const float* bih  = (const float*)d_in[3];
    const float* bhh  = (const float*)d_in[4];
    const float* Wout = (const float*)d_in[5];
    const float* bout = (const float*)d_in[6];
    float* out = (float*)d_out;

    cudaFuncSetAttribute(lstm_step0_kernel, cudaFuncAttributeMaxDynamicSharedMemorySize, S0_SMEM);
    cudaFuncSetAttribute(lstm_persist_kernel, cudaFuncAttributeMaxDynamicSharedMemorySize, PP_SMEM);
    cudaFuncSetAttribute(proj_kernel, cudaFuncAttributeMaxDynamicSharedMemorySize, PJ_SMEM);

    pack_kernel<<<(G4 * Hdim) / 256, 256>>>(Wih, Whh, bih, bhh, Wout, x);
    lstm_step0_kernel<<<dim3(32, 4), 256, S0_SMEM>>>();
    lstm_persist_kernel<<<256, 256, PP_SMEM>>>();
    proj_kernel<<<256, 512, PJ_SMEM>>>(bout, out);
}

// round 13
// speedup vs baseline: 1.4297x; 1.0908x over previous
#include <cuda_runtime.h>
#include <cuda_fp16.h>
#include <cstdint>

#define Bdim   256
#define Hdim   1024
#define G4     4096
#define Tsteps 128
#define DO     128
#define NCH    8                     // K chunks of 128
#define AT_EL  16384                 // 128 rows x 128 kin halves (32 KB)
#define WT_EL  8192                  // 64 rows x 128 kin halves (16 KB)

// ---------------- device scratch ------------------------------------------
__device__ __half g_B0[(size_t)G4 * Hdim];      // W_ih fp16, [nt32][c8][jl128][kin128]
__device__ __half g_Bc[(size_t)G4 * Hdim];      // (W_ih+W_hh) fp16, [nt64][c8][jl64][kin128]
__device__ __half g_xA[(size_t)Bdim * Hdim];    // x fp16, tiled
__device__ __half g_hf[(size_t)Tsteps * Bdim * Hdim]; // h fp16, [t][rt][c][rl][kin]
__device__ __half g_Wp[(size_t)DO * Hdim];      // W_out fp16, [c][d][kin]
__device__ float g_c[(size_t)Bdim * Hdim];      // cell state (step0 -> persist handoff)
__device__ float g_bp[G4];                      // bias, j = hcol*4+gate
__device__ unsigned g_flag[2][64];              // distributed barrier flags

// ---------------- helpers ---------------------------------------------------
__device__ __forceinline__ uint32_t smem_u32(const void* p) {
    uint32_t a;
    asm("{ .reg .u64 t; cvta.to.shared.u64 t, %1; cvt.u32.u64 %0, t; }" : "=r"(a) : "l"(p));
    return a;
}
__device__ __forceinline__ float sigf(float v)   { return 1.0f / (1.0f + __expf(-v)); }
__device__ __forceinline__ float tanhf_(float v) { return 2.0f / (1.0f + __expf(-2.0f * v)) - 1.0f; }

__device__ __forceinline__ void cpasync16(uint32_t dst, const void* src) {
    asm volatile("cp.async.cg.shared.global [%0], [%1], 16;" :: "r"(dst), "l"(src) : "memory");
}
__device__ __forceinline__ void cp_commit() { asm volatile("cp.async.commit_group;" ::: "memory"); }

__device__ __forceinline__ void ldm_x4(uint32_t* r, uint32_t addr) {
    asm volatile("ldmatrix.sync.aligned.m8n8.x4.shared.b16 {%0,%1,%2,%3}, [%4];"
                 : "=r"(r[0]), "=r"(r[1]), "=r"(r[2]), "=r"(r[3]) : "r"(addr));
}
__device__ __forceinline__ void mma_f16(float* d, const uint32_t* a, uint32_t b0, uint32_t b1) {
    asm volatile(
        "mma.sync.aligned.m16n8k16.row.col.f32.f16.f16.f32 "
        "{%0,%1,%2,%3}, {%4,%5,%6,%7}, {%8,%9}, {%0,%1,%2,%3};"
        : "+f"(d[0]), "+f"(d[1]), "+f"(d[2]), "+f"(d[3])
        : "r"(a[0]), "r"(a[1]), "r"(a[2]), "r"(a[3]), "r"(b0), "r"(b1));
}
// ldmatrix lane address into a 256B-row tile with per-8-row XOR swizzle
__device__ __forceinline__ uint32_t tile_addr2(uint32_t base, int row0, int k0, int lane) {
    int g = lane >> 3;
    int r = row0 + (lane & 7) + ((g & 1) << 3);
    int kE = k0 + ((g >> 1) << 3);
    return base + r * 256 + ((kE * 2) ^ ((r & 7) << 4));
}

// contention-free flag read: plain L2 load, NOT an atomic RMW
__device__ __forceinline__ unsigned ld_flag(const unsigned* p) {
    unsigned v;
    asm volatile("ld.global.cg.u32 %0, [%1];" : "=r"(v) : "l"(p) : "memory");
    return v;
}

// distributed-flag barrier: 64 CTAs per mt group, generation = t.
// Producers: fence + atomicExch (distinct addresses). Consumers: ld.cg poll
// with backoff — no atomic-ALU serialization at the LTS.
__device__ __forceinline__ void grid_bar(int mt, int cta, unsigned t) {
    __syncthreads();
    if (threadIdx.x == 0) {
        __threadfence();
        atomicExch(&g_flag[mt][cta], t);
    }
    if (threadIdx.x < 64) {
        if (ld_flag(&g_flag[mt][threadIdx.x]) < t) {
            while (ld_flag(&g_flag[mt][threadIdx.x]) < t) __nanosleep(32);
        }
        __threadfence();
    }
    __syncthreads();
}

// ---------------- pack kernel ----------------------------------------------
__global__ void pack_kernel(const float* __restrict__ Wih, const float* __restrict__ Whh,
                            const float* __restrict__ bih, const float* __restrict__ bhh,
                            const float* __restrict__ Wout, const float* __restrict__ x) {
    size_t idx = (size_t)blockIdx.x * 256 + threadIdx.x;   // 0 .. G4*Hdim-1
    {
        int j = (int)(idx >> 10), k = (int)(idx & 1023);
        int hcol = j >> 2, g = j & 3;
        size_t src = (size_t)(g * Hdim + hcol) * Hdim + k;
        float wi = Wih[src];
        size_t d0 = ((size_t)((j >> 7) * NCH + (k >> 7))) * AT_EL + (size_t)(j & 127) * 128 + (k & 127);
        g_B0[d0] = __float2half_rn(wi);
        size_t dc = ((size_t)((j >> 6) * NCH + (k >> 7))) * WT_EL + (size_t)(j & 63) * 128 + (k & 127);
        g_Bc[dc] = __float2half_rn(wi + Whh[src]);
    }
    if (idx < (size_t)Bdim * Hdim) {
        int r = (int)(idx >> 10), k = (int)(idx & 1023);
        size_t dst = ((size_t)((r >> 7) * NCH + (k >> 7))) * AT_EL + (size_t)(r & 127) * 128 + (k & 127);
        g_xA[dst] = __float2half_rn(x[idx]);
    }
    if (idx < G4) {
        int hcol = (int)idx >> 2, g = (int)idx & 3;
        g_bp[idx] = bih[g * Hdim + hcol] + bhh[g * Hdim + hcol];
    }
    if (idx < (size_t)Hdim * DO) {
        int k = (int)(idx >> 7), d = (int)(idx & (DO - 1));
        size_t dst = (size_t)(k >> 7) * AT_EL + (size_t)d * 128 + (k & 127);
        g_Wp[dst] = __float2half_rn(Wout[(size_t)d * Hdim + k]);
    }
    if (idx < 128)                          // reset barrier flags every launch
        ((unsigned*)g_flag)[idx] = 0u;
}

// ---------------- t = 0 step (streamed, 256 thr) -----------------------------
#define S0_STG 49152
#define S0_A   0
#define S0_B   16384
#define S0_SMEM (3 * S0_STG)

__global__ void __launch_bounds__(256, 1) lstm_step0_kernel() {
    extern __shared__ char smem[];
    const uint32_t sb = smem_u32(smem);
    const int tid = threadIdx.x;
    const int wid = tid >> 5, lane = tid & 31;
    const int nt = blockIdx.x, mt = blockIdx.y;
    const int rt = mt >> 1, rl0 = (mt & 1) * 64;

    const char* Aa = (const char*)(g_xA + (size_t)rt * NCH * AT_EL) + rl0 * 256;
    const char* Bp = (const char*)(g_B0 + (size_t)nt * NCH * AT_EL);

    auto issue = [&](int c) {
        if (c < NCH) {
            uint32_t stg = sb + (c % 3) * S0_STG;
            const char* pa = Aa + (size_t)c * AT_EL * 2;
            const char* pb = Bp + (size_t)c * AT_EL * 2;
            {
                int r = tid >> 2;
                #pragma unroll
                for (int p = 0; p < 4; p++) {
                    int kb = (tid & 3) * 16 + p * 64;
                    uint32_t sw = r * 256 + (kb ^ ((r & 7) << 4));
                    cpasync16(stg + S0_A + sw, pa + r * 256 + kb);
                }
            }
            {
                int r = tid >> 1;
                #pragma unroll
                for (int p = 0; p < 8; p++) {
                    int kb = (tid & 1) * 16 + p * 32;
                    uint32_t sw = r * 256 + (kb ^ ((r & 7) << 4));
                    cpasync16(stg + S0_B + sw, pb + r * 256 + kb);
                }
            }
        }
        cp_commit();
    };

    const int wr = wid >> 2, wc = wid & 3;
    const int mrow0 = wr * 32, n0 = wc * 32;

    float acc[2][4][4];
    #pragma unroll
    for (int mf = 0; mf < 2; mf++)
        #pragma unroll
        for (int nf = 0; nf < 4; nf++)
            #pragma unroll
            for (int q = 0; q < 4; q++) acc[mf][nf][q] = 0.0f;

    issue(0); issue(1);
    for (int c = 0; c < NCH; c++) {
        asm volatile("cp.async.wait_group 1;" ::: "memory");
        __syncthreads();
        uint32_t stg = sb + (c % 3) * S0_STG;

        uint32_t fa[2][2][4], fb[2][2][4];
        #pragma unroll
        for (int mf = 0; mf < 2; mf++)
            ldm_x4(fa[0][mf], tile_addr2(stg + S0_A, mrow0 + mf * 16, 0, lane));
        #pragma unroll
        for (int hf = 0; hf < 2; hf++)
            ldm_x4(fb[0][hf], tile_addr2(stg + S0_B, n0 + hf * 16, 0, lane));
        #pragma unroll
        for (int kst = 0; kst < 8; kst++) {
            const int cur = kst & 1, nxt = cur ^ 1;
            if (kst < 7) {
                const int k0 = (kst + 1) * 16;
                #pragma unroll
                for (int mf = 0; mf < 2; mf++)
                    ldm_x4(fa[nxt][mf], tile_addr2(stg + S0_A, mrow0 + mf * 16, k0, lane));
                #pragma unroll
                for (int hf = 0; hf < 2; hf++)
                    ldm_x4(fb[nxt][hf], tile_addr2(stg + S0_B, n0 + hf * 16, k0, lane));
            }
            #pragma unroll
            for (int mf = 0; mf < 2; mf++)
                #pragma unroll
                for (int nf = 0; nf < 4; nf++) {
                    const int hf = nf >> 1, lo = nf & 1;
                    mma_f16(acc[mf][nf], fa[cur][mf], fb[cur][hf][lo], fb[cur][hf][lo + 2]);
                }
        }
        issue(c + 2);
    }

    const int quad = lane >> 2, qp = lane & 3;
    const bool oddl = (lane & 1) != 0;
    const int mtb = mt * 64;

    #pragma unroll
    for (int mf = 0; mf < 2; mf++)
        #pragma unroll
        for (int nf = 0; nf < 4; nf++) {
            float* a = acc[mf][nf];
            int jb = nt * 128 + wc * 32 + nf * 8 + 2 * qp;
            float be = g_bp[jb], bo = g_bp[jb + 1];
            a[0] += be; a[1] += bo; a[2] += be; a[3] += bo;

            float p0 = __shfl_xor_sync(0xffffffffu, a[0], 1);
            float p1 = __shfl_xor_sync(0xffffffffu, a[1], 1);
            float p2 = __shfl_xor_sync(0xffffffffu, a[2], 1);
            float p3 = __shfl_xor_sync(0xffffffffu, a[3], 1);

            float vi = oddl ? p2 : a[0];
            float vf = oddl ? p3 : a[1];
            float vg = oddl ? a[2] : p0;
            float vo = oddl ? a[3] : p1;

            int row_g = mtb + wr * 32 + mf * 16 + quad + (oddl ? 8 : 0);
            int hc    = nt * 32 + wc * 8 + nf * 2 + (qp >> 1);

            float cn = sigf(vi) * tanhf_(vg);        // c0 = 0
            float hn = sigf(vo) * tanhf_(cn);
            g_c[(size_t)row_g * Hdim + hc] = cn;

            int rt2 = row_g >> 7, rl = row_g & 127;
            size_t hb = (((size_t)rt2 * NCH + (hc >> 7))) * AT_EL + (size_t)rl * 128 + (hc & 127);
            g_hf[hb] = __float2half_rn(hn);
        }
}

// ---------------- persistent kernel: steps 1..127, 512 threads ---------------
// 128 CTAs: nt = bid>>1 (64 gate cols), mt = bid&1 (128 rows).
// Warp grid: 4(row)x2(col)x2(k-half). Warp tile 32x32 over half the K range.
// SMEM: 3 streaming A stages (32K) + resident W 128K = 224K. Stage 0 doubles
// as the k-reduction scratch at step end.
#define P_STG_SZ 32768
#define P_OFF_W  (3 * P_STG_SZ)
#define P_SMEM   (P_OFF_W + 131072)      // 229376

__global__ void __launch_bounds__(512, 1) lstm_persist_kernel() {
    extern __shared__ char smem[];
    const uint32_t sb = smem_u32(smem);
    const int tid = threadIdx.x;
    const int wid = tid >> 5, lane = tid & 31;
    const int nt = blockIdx.x >> 1, mt = blockIdx.x & 1;
    const uint32_t sbW = sb + P_OFF_W;

    // resident fp16 weights: 8 chunks x (64 rows x 256B) = 128 KB
    {
        const char* wbase = (const char*)(g_Bc + (size_t)nt * NCH * WT_EL);
        for (int c = 0; c < NCH; c++) {
            const char* src = wbase + (size_t)c * WT_EL * 2;
            #pragma unroll
            for (int p = 0; p < 2; p++) {
                int r = (tid >> 4) + p * 32;
                int kb = (tid & 15) * 16;
                uint32_t sw = r * 256 + (kb ^ ((r & 7) << 4));
                cpasync16(sbW + c * 16384 + sw, src + r * 256 + kb);
            }
        }
        cp_commit();
        asm volatile("cp.async.wait_group 0;" ::: "memory");
        __syncthreads();
    }

    const int ks  = wid >> 3;            // k-half
    const int widL = wid & 7;
    const int wr = widL >> 1, wc = widL & 1;   // 4 row groups x 2 col groups
    const int mrow0 = wr * 32, n0 = wc * 32;
    const int kb0 = ks * 64;                   // this warp's k base within a chunk
    const int quad = lane >> 2, qp = lane & 3;
    const bool oddl = (lane & 1) != 0;
    const int sidx = widL * 32 + lane;         // scratch slot (same for paired warps)

    int rows[2], hcs[4];
    #pragma unroll
    for (int mf = 0; mf < 2; mf++)
        rows[mf] = mt * 128 + wr * 32 + mf * 16 + quad + (oddl ? 8 : 0);
    #pragma unroll
    for (int nf = 0; nf < 4; nf++)
        hcs[nf] = nt * 16 + wc * 8 + nf * 2 + (qp >> 1);

    float bias0[4], bias1[4], c_reg[2][4];
    if (ks == 0) {
        #pragma unroll
        for (int nf = 0; nf < 4; nf++) {
            int jb = nt * 64 + wc * 32 + nf * 8 + 2 * qp;
            bias0[nf] = g_bp[jb];
            bias1[nf] = g_bp[jb + 1];
            #pragma unroll
            for (int mf = 0; mf < 2; mf++)
                c_reg[mf][nf] = g_c[(size_t)rows[mf] * Hdim + hcs[nf]];
        }
    }

    float4* scr4 = (float4*)smem;              // stage-0 area reused as scratch

    for (int t = 1; t < Tsteps; t++) {
        const char* Aa = (const char*)(g_hf + ((size_t)(t - 1) * 2 + mt) * (NCH * AT_EL));

        auto issue = [&](int c) {
            if (c < NCH) {
                uint32_t stg = sb + (c % 3) * P_STG_SZ;
                const char* pa = Aa + (size_t)c * AT_EL * 2;
                int r = tid >> 2;
                #pragma unroll
                for (int p = 0; p < 4; p++) {
                    int kb = (tid & 3) * 16 + p * 64;
                    uint32_t sw = r * 256 + (kb ^ ((r & 7) << 4));
                    cpasync16(stg + sw, pa + r * 256 + kb);
                }
            }
            cp_commit();
        };

        float acc[2][4][4];
        #pragma unroll
        for (int mf = 0; mf < 2; mf++)
            #pragma unroll
            for (int nf = 0; nf < 4; nf++)
                #pragma unroll
                for (int q = 0; q < 4; q++) acc[mf][nf][q] = 0.0f;

        issue(0); issue(1);
        for (int c = 0; c < NCH; c++) {
            asm volatile("cp.async.wait_group 1;" ::: "memory");
            __syncthreads();
            uint32_t stg = sb + (c % 3) * P_STG_SZ;
            uint32_t wch = sbW + c * 16384;

            uint32_t fa[2][2][4], fw[2][2][4];
            #pragma unroll
            for (int mf = 0; mf < 2; mf++)
                ldm_x4(fa[0][mf], tile_addr2(stg, mrow0 + mf * 16, kb0, lane));
            #pragma unroll
            for (int hf = 0; hf < 2; hf++)
                ldm_x4(fw[0][hf], tile_addr2(wch, n0 + hf * 16, kb0, lane));

            #pragma unroll
            for (int kst = 0; kst < 4; kst++) {
                const int cur = kst & 1, nxt = cur ^ 1;
                if (kst < 3) {
                    const int k0 = kb0 + (kst + 1) * 16;
                    #pragma unroll
                    for (int mf = 0; mf < 2; mf++)
                        ldm_x4(fa[nxt][mf], tile_addr2(stg, mrow0 + mf * 16, k0, lane));
                    #pragma unroll
                    for (int hf = 0; hf < 2; hf++)
                        ldm_x4(fw[nxt][hf], tile_addr2(wch, n0 + hf * 16, k0, lane));
                }
                #pragma unroll
                for (int mf = 0; mf < 2; mf++)
                    #pragma unroll
                    for (int nf = 0; nf < 4; nf++) {
                        const int hf = nf >> 1, lo = nf & 1;
                        mma_f16(acc[mf][nf], fa[cur][mf], fw[cur][hf][lo], fw[cur][hf][lo + 2]);
                    }
            }
            issue(c + 2);
        }

        // ---- k-half reduction (scratch = stage 0, free after last chunk sync) ----
        if (ks == 1) {
            #pragma unroll
            for (int mf = 0; mf < 2; mf++)
                #pragma unroll
                for (int nf = 0; nf < 4; nf++)
                    scr4[(mf * 4 + nf) * 256 + sidx] =
                        make_float4(acc[mf][nf][0], acc[mf][nf][1], acc[mf][nf][2], acc[mf][nf][3]);
        }
        __syncthreads();

        // ---- LSTM cell epilogue (k-half 0 warps) ----
        if (ks == 0) {
            #pragma unroll
            for (int mf = 0; mf < 2; mf++)
                #pragma unroll
                for (int nf = 0; nf < 4; nf++) {
                    float* a = acc[mf][nf];
                    float4 rd = scr4[(mf * 4 + nf) * 256 + sidx];
                    a[0] += rd.x + bias0[nf];
                    a[1] += rd.y + bias1[nf];
                    a[2] += rd.z + bias0[nf];
                    a[3] += rd.w + bias1[nf];

                    float p0 = __shfl_xor_sync(0xffffffffu, a[0], 1);
                    float p1 = __shfl_xor_sync(0xffffffffu, a[1], 1);
                    float p2 = __shfl_xor_sync(0xffffffffu, a[2], 1);
                    float p3 = __shfl_xor_sync(0xffffffffu, a[3], 1);

                    float vi = oddl ? p2 : a[0];
                    float vf = oddl ? p3 : a[1];
                    float vg = oddl ? a[2] : p0;
                    float vo = oddl ? a[3] : p1;

                    float cn = sigf(vf) * c_reg[mf][nf] + sigf(vi) * tanhf_(vg);
                    float hn = sigf(vo) * tanhf_(cn);
                    c_reg[mf][nf] = cn;

                    int row_g = rows[mf], hc = hcs[nf];
                    int rl = row_g & 127;
                    size_t hb = (((size_t)t * 2 + mt) * NCH + (hc >> 7)) * AT_EL
                              + (size_t)rl * 128 + (hc & 127);
                    g_hf[hb] = __float2half_rn(hn);
                }
        }

        if (t < Tsteps - 1) grid_bar(mt, nt, (unsigned)t);
    }
}

// ---------------- projection (fp16 HMMA) -------------------------------------
#define PJ_STG 65536
#define PJ_A   0
#define PJ_B   32768
#define PJ_SMEM (3 * PJ_STG)

__global__ void __launch_bounds__(512, 1) proj_kernel(const float* __restrict__ bout,
                                                      float* __restrict__ out) {
    extern __shared__ char smem[];
    const uint32_t sb = smem_u32(smem);
    const int tid = threadIdx.x;
    const int wid = tid >> 5, lane = tid & 31;
    const int t = blockIdx.x >> 1, rt = blockIdx.x & 1;

    const char* Aa = (const char*)(g_hf + ((size_t)t * 2 + rt) * (NCH * AT_EL));

    auto issue = [&](int c) {
        if (c < NCH) {
            uint32_t stg = sb + (c % 3) * PJ_STG;
            const char* pa = Aa + (size_t)c * AT_EL * 2;
            const char* pb = (const char*)(g_Wp + (size_t)c * AT_EL);
            int r = tid >> 2;
            #pragma unroll
            for (int p = 0; p < 4; p++) {
                int kb = (tid & 3) * 16 + p * 64;
                uint32_t sw = r * 256 + (kb ^ ((r & 7) << 4));
                cpasync16(stg + PJ_A + sw, pa + r * 256 + kb);
                cpasync16(stg + PJ_B + sw, pb + r * 256 + kb);
            }
        }
        cp_commit();
    };

    const int wr = wid >> 2, wc = wid & 3;     // warp = 32 rows x 32 cols
    const int mrow0 = wr * 32, n0 = wc * 32;

    float acc[2][4][4];
    #pragma unroll
    for (int mf = 0; mf < 2; mf++)
        #pragma unroll
        for (int nf = 0; nf < 4; nf++)
            #pragma unroll
            for (int q = 0; q < 4; q++) acc[mf][nf][q] = 0.0f;

    issue(0); issue(1);
    for (int c = 0; c < NCH; c++) {
        asm volatile("cp.async.wait_group 1;" ::: "memory");
        __syncthreads();
        uint32_t stg = sb + (c % 3) * PJ_STG;

        uint32_t fa[2][2][4], fb[2][2][4];
        #pragma unroll
        for (int mf = 0; mf < 2; mf++)
            ldm_x4(fa[0][mf], tile_addr2(stg + PJ_A, mrow0 + mf * 16, 0, lane));
        #pragma unroll
        for (int hf = 0; hf < 2; hf++)
            ldm_x4(fb[0][hf], tile_addr2(stg + PJ_B, n0 + hf * 16, 0, lane));
        #pragma unroll
        for (int kst = 0; kst < 8; kst++) {
            const int cur = kst & 1, nxt = cur ^ 1;
            if (kst < 7) {
                const int k0 = (kst + 1) * 16;
                #pragma unroll
                for (int mf = 0; mf < 2; mf++)
                    ldm_x4(fa[nxt][mf], tile_addr2(stg + PJ_A, mrow0 + mf * 16, k0, lane));
                #pragma unroll
                for (int hf = 0; hf < 2; hf++)
                    ldm_x4(fb[nxt][hf], tile_addr2(stg + PJ_B, n0 + hf * 16, k0, lane));
            }
            #pragma unroll
            for (int mf = 0; mf < 2; mf++)
                #pragma unroll
                for (int nf = 0; nf < 4; nf++) {
                    const int hf = nf >> 1, lo = nf & 1;
                    mma_f16(acc[mf][nf], fa[cur][mf], fb[cur][hf][lo], fb[cur][hf][lo + 2]);
                }
        }
        issue(c + 2);
    }

    const int quad = lane >> 2, qp = lane & 3;
    #pragma unroll
    for (int mf = 0; mf < 2; mf++)
        #pragma unroll
        for (int nf = 0; nf < 4; nf++) {
            float* a = acc[mf][nf];
            int col = wc * 32 + nf * 8 + 2 * qp;
            float be = bout[col], bo = bout[col + 1];
            int row0 = wr * 32 + mf * 16 + quad;
            int b0 = rt * 128 + row0;
            float2 v0 = make_float2(a[0] + be, a[1] + bo);
            float2 v1 = make_float2(a[2] + be, a[3] + bo);
            *(float2*)&out[((size_t)b0 * Tsteps + t) * DO + col] = v0;
            *(float2*)&out[((size_t)(b0 + 8) * Tsteps + t) * DO + col] = v1;
        }
}

// ---------------- launcher ---------------------------------------------------
extern "C" void kernel_launch(void* const* d_in, const int* in_sizes, int n_in,
                              void* d_out, int out_size) {
    const float* x    = (const float*)d_in[0];
    const float* Wih  = (const float*)d_in[1];
    const float* Whh  = (const float*)d_in[2];
    const float* bih  = (const float*)d_in[3];
    const float* bhh  = (const float*)d_in[4];
    const float* Wout = (const float*)d_in[5];
    const float* bout = (const float*)d_in[6];
    float* out = (float*)d_out;

    cudaFuncSetAttribute(lstm_step0_kernel, cudaFuncAttributeMaxDynamicSharedMemorySize, S0_SMEM);
    cudaFuncSetAttribute(lstm_persist_kernel, cudaFuncAttributeMaxDynamicSharedMemorySize, P_SMEM);
    cudaFuncSetAttribute(proj_kernel, cudaFuncAttributeMaxDynamicSharedMemorySize, PJ_SMEM);

    pack_kernel<<<(G4 * Hdim) / 256, 256>>>(Wih, Whh, bih, bhh, Wout, x);
    lstm_step0_kernel<<<dim3(32, 4), 256, S0_SMEM>>>();
    lstm_persist_kernel<<<128, 512, P_SMEM>>>();
    proj_kernel<<<256, 512, PJ_SMEM>>>(bout, out);
}

// round 14
// speedup vs baseline: 1.4399x; 1.0072x over previous
#include <cuda_runtime.h>
#include <cuda_fp16.h>
#include <cstdint>

#define Bdim   256
#define Hdim   1024
#define G4     4096
#define Tsteps 128
#define DO     128
#define NCH    8                     // K chunks of 128
#define AT_EL  16384                 // 128 rows x 128 kin halves (32 KB)
#define WT_EL  8192                  // 64 rows x 128 kin halves (16 KB)

// ---------------- device scratch ------------------------------------------
__device__ __half g_B0[(size_t)G4 * Hdim];      // W_ih fp16, [nt32][c8][jl128][kin128]
__device__ __half g_Bc[(size_t)G4 * Hdim];      // (W_ih+W_hh) fp16, [nt64][c8][jl64][kin128]
__device__ __half g_xA[(size_t)Bdim * Hdim];    // x fp16, tiled
__device__ __half g_hf[(size_t)Tsteps * Bdim * Hdim]; // h fp16, [t][rt][c][rl][kin]
__device__ __half g_Wp[(size_t)DO * Hdim];      // W_out fp16, [c][d][kin]
__device__ float g_c[(size_t)Bdim * Hdim];      // cell state (step0 -> persist handoff)
__device__ float g_bp[G4];                      // bias, j = hcol*4+gate
__device__ unsigned g_flag[2][64];              // distributed barrier flags

// ---------------- helpers ---------------------------------------------------
__device__ __forceinline__ uint32_t smem_u32(const void* p) {
    uint32_t a;
    asm("{ .reg .u64 t; cvta.to.shared.u64 t, %1; cvt.u32.u64 %0, t; }" : "=r"(a) : "l"(p));
    return a;
}
__device__ __forceinline__ float sigf(float v)   { return 1.0f / (1.0f + __expf(-v)); }
__device__ __forceinline__ float tanhf_(float v) { return 2.0f / (1.0f + __expf(-2.0f * v)) - 1.0f; }

__device__ __forceinline__ void cpasync16(uint32_t dst, const void* src) {
    asm volatile("cp.async.cg.shared.global [%0], [%1], 16;" :: "r"(dst), "l"(src) : "memory");
}
__device__ __forceinline__ void cp_commit() { asm volatile("cp.async.commit_group;" ::: "memory"); }

__device__ __forceinline__ void ldm_x4(uint32_t* r, uint32_t addr) {
    asm volatile("ldmatrix.sync.aligned.m8n8.x4.shared.b16 {%0,%1,%2,%3}, [%4];"
                 : "=r"(r[0]), "=r"(r[1]), "=r"(r[2]), "=r"(r[3]) : "r"(addr));
}
__device__ __forceinline__ void mma_f16(float* d, const uint32_t* a, uint32_t b0, uint32_t b1) {
    asm volatile(
        "mma.sync.aligned.m16n8k16.row.col.f32.f16.f16.f32 "
        "{%0,%1,%2,%3}, {%4,%5,%6,%7}, {%8,%9}, {%0,%1,%2,%3};"
        : "+f"(d[0]), "+f"(d[1]), "+f"(d[2]), "+f"(d[3])
        : "r"(a[0]), "r"(a[1]), "r"(a[2]), "r"(a[3]), "r"(b0), "r"(b1));
}
// ldmatrix lane address into a 256B-row tile with per-8-row XOR swizzle
__device__ __forceinline__ uint32_t tile_addr2(uint32_t base, int row0, int k0, int lane) {
    int g = lane >> 3;
    int r = row0 + (lane & 7) + ((g & 1) << 3);
    int kE = k0 + ((g >> 1) << 3);
    return base + r * 256 + ((kE * 2) ^ ((r & 7) << 4));
}

// contention-free flag read: plain L2 load, NOT an atomic RMW
__device__ __forceinline__ unsigned ld_flag(const unsigned* p) {
    unsigned v;
    asm volatile("ld.global.cg.u32 %0, [%1];" : "=r"(v) : "l"(p) : "memory");
    return v;
}

// distributed-flag barrier: 64 CTAs per mt group, generation = t
__device__ __forceinline__ void grid_bar(int mt, int cta, unsigned t) {
    __syncthreads();
    if (threadIdx.x == 0) {
        __threadfence();
        atomicExch(&g_flag[mt][cta], t);
    }
    if (threadIdx.x < 64) {
        if (ld_flag(&g_flag[mt][threadIdx.x]) < t) {
            while (ld_flag(&g_flag[mt][threadIdx.x]) < t) __nanosleep(32);
        }
        __threadfence();
    }
    __syncthreads();
}

// ---------------- pack kernel ----------------------------------------------
__global__ void pack_kernel(const float* __restrict__ Wih, const float* __restrict__ Whh,
                            const float* __restrict__ bih, const float* __restrict__ bhh,
                            const float* __restrict__ Wout, const float* __restrict__ x) {
    size_t idx = (size_t)blockIdx.x * 256 + threadIdx.x;   // 0 .. G4*Hdim-1
    {
        int j = (int)(idx >> 10), k = (int)(idx & 1023);
        int hcol = j >> 2, g = j & 3;
        size_t src = (size_t)(g * Hdim + hcol) * Hdim + k;
        float wi = Wih[src];
        size_t d0 = ((size_t)((j >> 7) * NCH + (k >> 7))) * AT_EL + (size_t)(j & 127) * 128 + (k & 127);
        g_B0[d0] = __float2half_rn(wi);
        size_t dc = ((size_t)((j >> 6) * NCH + (k >> 7))) * WT_EL + (size_t)(j & 63) * 128 + (k & 127);
        g_Bc[dc] = __float2half_rn(wi + Whh[src]);
    }
    if (idx < (size_t)Bdim * Hdim) {
        int r = (int)(idx >> 10), k = (int)(idx & 1023);
        size_t dst = ((size_t)((r >> 7) * NCH + (k >> 7))) * AT_EL + (size_t)(r & 127) * 128 + (k & 127);
        g_xA[dst] = __float2half_rn(x[idx]);
    }
    if (idx < G4) {
        int hcol = (int)idx >> 2, g = (int)idx & 3;
        g_bp[idx] = bih[g * Hdim + hcol] + bhh[g * Hdim + hcol];
    }
    if (idx < (size_t)Hdim * DO) {
        int k = (int)(idx >> 7), d = (int)(idx & (DO - 1));
        size_t dst = (size_t)(k >> 7) * AT_EL + (size_t)d * 128 + (k & 127);
        g_Wp[dst] = __float2half_rn(Wout[(size_t)d * Hdim + k]);
    }
    if (idx < 128)                          // reset barrier flags every launch
        ((unsigned*)g_flag)[idx] = 0u;
}

// ---------------- t = 0 step (streamed, 256 thr) -----------------------------
#define S0_STG 49152
#define S0_A   0
#define S0_B   16384
#define S0_SMEM (3 * S0_STG)

__global__ void __launch_bounds__(256, 1) lstm_step0_kernel() {
    extern __shared__ char smem[];
    const uint32_t sb = smem_u32(smem);
    const int tid = threadIdx.x;
    const int wid = tid >> 5, lane = tid & 31;
    const int nt = blockIdx.x, mt = blockIdx.y;
    const int rt = mt >> 1, rl0 = (mt & 1) * 64;

    const char* Aa = (const char*)(g_xA + (size_t)rt * NCH * AT_EL) + rl0 * 256;
    const char* Bp = (const char*)(g_B0 + (size_t)nt * NCH * AT_EL);

    auto issue = [&](int c) {
        if (c < NCH) {
            uint32_t stg = sb + (c % 3) * S0_STG;
            const char* pa = Aa + (size_t)c * AT_EL * 2;
            const char* pb = Bp + (size_t)c * AT_EL * 2;
            {
                int r = tid >> 2;
                #pragma unroll
                for (int p = 0; p < 4; p++) {
                    int kb = (tid & 3) * 16 + p * 64;
                    uint32_t sw = r * 256 + (kb ^ ((r & 7) << 4));
                    cpasync16(stg + S0_A + sw, pa + r * 256 + kb);
                }
            }
            {
                int r = tid >> 1;
                #pragma unroll
                for (int p = 0; p < 8; p++) {
                    int kb = (tid & 1) * 16 + p * 32;
                    uint32_t sw = r * 256 + (kb ^ ((r & 7) << 4));
                    cpasync16(stg + S0_B + sw, pb + r * 256 + kb);
                }
            }
        }
        cp_commit();
    };

    const int wr = wid >> 2, wc = wid & 3;
    const int mrow0 = wr * 32, n0 = wc * 32;

    float acc[2][4][4];
    #pragma unroll
    for (int mf = 0; mf < 2; mf++)
        #pragma unroll
        for (int nf = 0; nf < 4; nf++)
            #pragma unroll
            for (int q = 0; q < 4; q++) acc[mf][nf][q] = 0.0f;

    issue(0); issue(1);
    for (int c = 0; c < NCH; c++) {
        asm volatile("cp.async.wait_group 1;" ::: "memory");
        __syncthreads();
        uint32_t stg = sb + (c % 3) * S0_STG;

        uint32_t fa[2][2][4], fb[2][2][4];
        #pragma unroll
        for (int mf = 0; mf < 2; mf++)
            ldm_x4(fa[0][mf], tile_addr2(stg + S0_A, mrow0 + mf * 16, 0, lane));
        #pragma unroll
        for (int hf = 0; hf < 2; hf++)
            ldm_x4(fb[0][hf], tile_addr2(stg + S0_B, n0 + hf * 16, 0, lane));
        #pragma unroll
        for (int kst = 0; kst < 8; kst++) {
            const int cur = kst & 1, nxt = cur ^ 1;
            if (kst < 7) {
                const int k0 = (kst + 1) * 16;
                #pragma unroll
                for (int mf = 0; mf < 2; mf++)
                    ldm_x4(fa[nxt][mf], tile_addr2(stg + S0_A, mrow0 + mf * 16, k0, lane));
                #pragma unroll
                for (int hf = 0; hf < 2; hf++)
                    ldm_x4(fb[nxt][hf], tile_addr2(stg + S0_B, n0 + hf * 16, k0, lane));
            }
            #pragma unroll
            for (int mf = 0; mf < 2; mf++)
                #pragma unroll
                for (int nf = 0; nf < 4; nf++) {
                    const int hf = nf >> 1, lo = nf & 1;
                    mma_f16(acc[mf][nf], fa[cur][mf], fb[cur][hf][lo], fb[cur][hf][lo + 2]);
                }
        }
        issue(c + 2);
    }

    const int quad = lane >> 2, qp = lane & 3;
    const bool oddl = (lane & 1) != 0;
    const int mtb = mt * 64;

    #pragma unroll
    for (int mf = 0; mf < 2; mf++)
        #pragma unroll
        for (int nf = 0; nf < 4; nf++) {
            float* a = acc[mf][nf];
            int jb = nt * 128 + wc * 32 + nf * 8 + 2 * qp;
            float be = g_bp[jb], bo = g_bp[jb + 1];
            a[0] += be; a[1] += bo; a[2] += be; a[3] += bo;

            float p0 = __shfl_xor_sync(0xffffffffu, a[0], 1);
            float p1 = __shfl_xor_sync(0xffffffffu, a[1], 1);
            float p2 = __shfl_xor_sync(0xffffffffu, a[2], 1);
            float p3 = __shfl_xor_sync(0xffffffffu, a[3], 1);

            float vi = oddl ? p2 : a[0];
            float vf = oddl ? p3 : a[1];
            float vg = oddl ? a[2] : p0;
            float vo = oddl ? a[3] : p1;

            int row_g = mtb + wr * 32 + mf * 16 + quad + (oddl ? 8 : 0);
            int hc    = nt * 32 + wc * 8 + nf * 2 + (qp >> 1);

            float cn = sigf(vi) * tanhf_(vg);        // c0 = 0
            float hn = sigf(vo) * tanhf_(cn);
            g_c[(size_t)row_g * Hdim + hc] = cn;

            int rt2 = row_g >> 7, rl = row_g & 127;
            size_t hb = (((size_t)rt2 * NCH + (hc >> 7))) * AT_EL + (size_t)rl * 128 + (hc & 127);
            g_hf[hb] = __float2half_rn(hn);
        }
}

// ---------------- persistent kernel: steps 1..127, 512 threads ---------------
// 128 CTAs: nt = bid>>1 (64 gate cols), mt = bid&1 (128 rows).
// Warp grid: 4(row)x2(col)x2(k-half). Warp tile 32x32 over half the K range.
// SMEM: 3 streaming A stages (32K) + resident W 128K = 224K.
// Stage 0 = k-reduction scratch; stage 1 (first 4KB) = h staging tile.
#define P_STG_SZ 32768
#define P_OFF_W  (3 * P_STG_SZ)
#define P_SMEM   (P_OFF_W + 131072)      // 229376

__global__ void __launch_bounds__(512, 1) lstm_persist_kernel() {
    extern __shared__ char smem[];
    const uint32_t sb = smem_u32(smem);
    const int tid = threadIdx.x;
    const int wid = tid >> 5, lane = tid & 31;
    const int nt = blockIdx.x >> 1, mt = blockIdx.x & 1;
    const uint32_t sbW = sb + P_OFF_W;

    // resident fp16 weights: 8 chunks x (64 rows x 256B) = 128 KB
    {
        const char* wbase = (const char*)(g_Bc + (size_t)nt * NCH * WT_EL);
        for (int c = 0; c < NCH; c++) {
            const char* src = wbase + (size_t)c * WT_EL * 2;
            #pragma unroll
            for (int p = 0; p < 2; p++) {
                int r = (tid >> 4) + p * 32;
                int kb = (tid & 15) * 16;
                uint32_t sw = r * 256 + (kb ^ ((r & 7) << 4));
                cpasync16(sbW + c * 16384 + sw, src + r * 256 + kb);
            }
        }
        cp_commit();
        asm volatile("cp.async.wait_group 0;" ::: "memory");
        __syncthreads();
    }

    const int ks  = wid >> 3;            // k-half
    const int widL = wid & 7;
    const int wr = widL >> 1, wc = widL & 1;   // 4 row groups x 2 col groups
    const int mrow0 = wr * 32, n0 = wc * 32;
    const int kb0 = ks * 64;
    const int quad = lane >> 2, qp = lane & 3;
    const bool oddl = (lane & 1) != 0;
    const int sidx = widL * 32 + lane;         // scratch slot (same for paired warps)

    int rows[2], hcs[4];
    #pragma unroll
    for (int mf = 0; mf < 2; mf++)
        rows[mf] = mt * 128 + wr * 32 + mf * 16 + quad + (oddl ? 8 : 0);
    #pragma unroll
    for (int nf = 0; nf < 4; nf++)
        hcs[nf] = nt * 16 + wc * 8 + nf * 2 + (qp >> 1);

    // local coords for h staging tile
    int lrow[2], lcol[4];
    #pragma unroll
    for (int mf = 0; mf < 2; mf++)
        lrow[mf] = wr * 32 + mf * 16 + quad + (oddl ? 8 : 0);       // 0..127
    #pragma unroll
    for (int nf = 0; nf < 4; nf++)
        lcol[nf] = wc * 8 + nf * 2 + (qp >> 1);                      // 0..15

    float bias0[4], bias1[4], c_reg[2][4];
    if (ks == 0) {
        #pragma unroll
        for (int nf = 0; nf < 4; nf++) {
            int jb = nt * 64 + wc * 32 + nf * 8 + 2 * qp;
            bias0[nf] = g_bp[jb];
            bias1[nf] = g_bp[jb + 1];
            #pragma unroll
            for (int mf = 0; mf < 2; mf++)
                c_reg[mf][nf] = g_c[(size_t)rows[mf] * Hdim + hcs[nf]];
        }
    }

    float4* scr4 = (float4*)smem;                       // stage 0: k-half scratch
    __half* hsm  = (__half*)(smem + P_STG_SZ);          // stage 1: h tile [128][16]

    // precomputed coalesced h-store slot for this thread (tid<256)
    const int st_r = tid >> 1, st_h = tid & 1;
    const size_t hb_base = (size_t)mt * 0 /* placeholder */;
    const size_t hb_fixed = ((size_t)(nt >> 3)) * AT_EL + (size_t)st_r * 128 + (nt & 7) * 16 + st_h * 8;

    for (int t = 1; t < Tsteps; t++) {
        const char* Aa = (const char*)(g_hf + ((size_t)(t - 1) * 2 + mt) * (NCH * AT_EL));

        auto issue = [&](int c) {
            if (c < NCH) {
                uint32_t stg = sb + (c % 3) * P_STG_SZ;
                const char* pa = Aa + (size_t)c * AT_EL * 2;
                int r = tid >> 2;
                #pragma unroll
                for (int p = 0; p < 4; p++) {
                    int kb = (tid & 3) * 16 + p * 64;
                    uint32_t sw = r * 256 + (kb ^ ((r & 7) << 4));
                    cpasync16(stg + sw, pa + r * 256 + kb);
                }
            }
            cp_commit();
        };

        float acc[2][4][4];
        #pragma unroll
        for (int mf = 0; mf < 2; mf++)
            #pragma unroll
            for (int nf = 0; nf < 4; nf++)
                #pragma unroll
                for (int q = 0; q < 4; q++) acc[mf][nf][q] = 0.0f;

        issue(0); issue(1);
        for (int c = 0; c < NCH; c++) {
            asm volatile("cp.async.wait_group 1;" ::: "memory");
            __syncthreads();
            uint32_t stg = sb + (c % 3) * P_STG_SZ;
            uint32_t wch = sbW + c * 16384;

            uint32_t fa[2][2][4], fw[2][2][4];
            #pragma unroll
            for (int mf = 0; mf < 2; mf++)
                ldm_x4(fa[0][mf], tile_addr2(stg, mrow0 + mf * 16, kb0, lane));
            #pragma unroll
            for (int hf = 0; hf < 2; hf++)
                ldm_x4(fw[0][hf], tile_addr2(wch, n0 + hf * 16, kb0, lane));

            #pragma unroll
            for (int kst = 0; kst < 4; kst++) {
                const int cur = kst & 1, nxt = cur ^ 1;
                if (kst < 3) {
                    const int k0 = kb0 + (kst + 1) * 16;
                    #pragma unroll
                    for (int mf = 0; mf < 2; mf++)
                        ldm_x4(fa[nxt][mf], tile_addr2(stg, mrow0 + mf * 16, k0, lane));
                    #pragma unroll
                    for (int hf = 0; hf < 2; hf++)
                        ldm_x4(fw[nxt][hf], tile_addr2(wch, n0 + hf * 16, k0, lane));
                }
                #pragma unroll
                for (int mf = 0; mf < 2; mf++)
                    #pragma unroll
                    for (int nf = 0; nf < 4; nf++) {
                        const int hf = nf >> 1, lo = nf & 1;
                        mma_f16(acc[mf][nf], fa[cur][mf], fw[cur][hf][lo], fw[cur][hf][lo + 2]);
                    }
            }
            issue(c + 2);
        }

        // ---- k-half reduction (scratch = stage 0, free after last chunk sync) ----
        if (ks == 1) {
            #pragma unroll
            for (int mf = 0; mf < 2; mf++)
                #pragma unroll
                for (int nf = 0; nf < 4; nf++)
                    scr4[(mf * 4 + nf) * 256 + sidx] =
                        make_float4(acc[mf][nf][0], acc[mf][nf][1], acc[mf][nf][2], acc[mf][nf][3]);
        }
        __syncthreads();

        // ---- LSTM cell epilogue: stage h into SMEM (k-half 0 warps) ----
        if (ks == 0) {
            #pragma unroll
            for (int mf = 0; mf < 2; mf++)
                #pragma unroll
                for (int nf = 0; nf < 4; nf++) {
                    float* a = acc[mf][nf];
                    float4 rd = scr4[(mf * 4 + nf) * 256 + sidx];
                    a[0] += rd.x + bias0[nf];
                    a[1] += rd.y + bias1[nf];
                    a[2] += rd.z + bias0[nf];
                    a[3] += rd.w + bias1[nf];

                    float p0 = __shfl_xor_sync(0xffffffffu, a[0], 1);
                    float p1 = __shfl_xor_sync(0xffffffffu, a[1], 1);
                    float p2 = __shfl_xor_sync(0xffffffffu, a[2], 1);
                    float p3 = __shfl_xor_sync(0xffffffffu, a[3], 1);

                    float vi = oddl ? p2 : a[0];
                    float vf = oddl ? p3 : a[1];
                    float vg = oddl ? a[2] : p0;
                    float vo = oddl ? a[3] : p1;

                    float cn = sigf(vf) * c_reg[mf][nf] + sigf(vi) * tanhf_(vg);
                    float hn = sigf(vo) * tanhf_(cn);
                    c_reg[mf][nf] = cn;

                    hsm[lrow[mf] * 16 + lcol[nf]] = __float2half_rn(hn);
                }
        }
        __syncthreads();

        // ---- coalesced h store: 256 threads x 16B ----
        if (tid < 256) {
            uint4 v = *(uint4*)(hsm + st_r * 16 + st_h * 8);
            __half* dst = g_hf + ((size_t)t * 2 + mt) * (NCH * AT_EL) + hb_fixed;
            *(uint4*)dst = v;
        }
        (void)hb_base;

        if (t < Tsteps - 1) grid_bar(mt, nt, (unsigned)t);
    }
}

// ---------------- projection (fp16 HMMA) -------------------------------------
#define PJ_STG 65536
#define PJ_A   0
#define PJ_B   32768
#define PJ_SMEM (3 * PJ_STG)

__global__ void __launch_bounds__(512, 1) proj_kernel(const float* __restrict__ bout,
                                                      float* __restrict__ out) {
    extern __shared__ char smem[];
    const uint32_t sb = smem_u32(smem);
    const int tid = threadIdx.x;
    const int wid = tid >> 5, lane = tid & 31;
    const int t = blockIdx.x >> 1, rt = blockIdx.x & 1;

    const char* Aa = (const char*)(g_hf + ((size_t)t * 2 + rt) * (NCH * AT_EL));

    auto issue = [&](int c) {
        if (c < NCH) {
            uint32_t stg = sb + (c % 3) * PJ_STG;
            const char* pa = Aa + (size_t)c * AT_EL * 2;
            const char* pb = (const char*)(g_Wp + (size_t)c * AT_EL);
            int r = tid >> 2;
            #pragma unroll
            for (int p = 0; p < 4; p++) {
                int kb = (tid & 3) * 16 + p * 64;
                uint32_t sw = r * 256 + (kb ^ ((r & 7) << 4));
                cpasync16(stg + PJ_A + sw, pa + r * 256 + kb);
                cpasync16(stg + PJ_B + sw, pb + r * 256 + kb);
            }
        }
        cp_commit();
    };

    const int wr = wid >> 2, wc = wid & 3;     // warp = 32 rows x 32 cols
    const int mrow0 = wr * 32, n0 = wc * 32;

    float acc[2][4][4];
    #pragma unroll
    for (int mf = 0; mf < 2; mf++)
        #pragma unroll
        for (int nf = 0; nf < 4; nf++)
            #pragma unroll
            for (int q = 0; q < 4; q++) acc[mf][nf][q] = 0.0f;

    issue(0); issue(1);
    for (int c = 0; c < NCH; c++) {
        asm volatile("cp.async.wait_group 1;" ::: "memory");
        __syncthreads();
        uint32_t stg = sb + (c % 3) * PJ_STG;

        uint32_t fa[2][2][4], fb[2][2][4];
        #pragma unroll
        for (int mf = 0; mf < 2; mf++)
            ldm_x4(fa[0][mf], tile_addr2(stg + PJ_A, mrow0 + mf * 16, 0, lane));
        #pragma unroll
        for (int hf = 0; hf < 2; hf++)
            ldm_x4(fb[0][hf], tile_addr2(stg + PJ_B, n0 + hf * 16, 0, lane));
        #pragma unroll
        for (int kst = 0; kst < 8; kst++) {
            const int cur = kst & 1, nxt = cur ^ 1;
            if (kst < 7) {
                const int k0 = (kst + 1) * 16;
                #pragma unroll
                for (int mf = 0; mf < 2; mf++)
                    ldm_x4(fa[nxt][mf], tile_addr2(stg + PJ_A, mrow0 + mf * 16, k0, lane));
                #pragma unroll
                for (int hf = 0; hf < 2; hf++)
                    ldm_x4(fb[nxt][hf], tile_addr2(stg + PJ_B, n0 + hf * 16, k0, lane));
            }
            #pragma unroll
            for (int mf = 0; mf < 2; mf++)
                #pragma unroll
                for (int nf = 0; nf < 4; nf++) {
                    const int hf = nf >> 1, lo = nf & 1;
                    mma_f16(acc[mf][nf], fa[cur][mf], fb[cur][hf][lo], fb[cur][hf][lo + 2]);
                }
        }
        issue(c + 2);
    }

    const int quad = lane >> 2, qp = lane & 3;
    #pragma unroll
    for (int mf = 0; mf < 2; mf++)
        #pragma unroll
        for (int nf = 0; nf < 4; nf++) {
            float* a = acc[mf][nf];
            int col = wc * 32 + nf * 8 + 2 * qp;
            float be = bout[col], bo = bout[col + 1];
            int row0 = wr * 32 + mf * 16 + quad;
            int b0 = rt * 128 + row0;
            float2 v0 = make_float2(a[0] + be, a[1] + bo);
            float2 v1 = make_float2(a[2] + be, a[3] + bo);
            *(float2*)&out[((size_t)b0 * Tsteps + t) * DO + col] = v0;
            *(float2*)&out[((size_t)(b0 + 8) * Tsteps + t) * DO + col] = v1;
        }
}

// ---------------- launcher ---------------------------------------------------
extern "C" void kernel_launch(void* const* d_in, const int* in_sizes, int n_in,
                              void* d_out, int out_size) {
    const float* x    = (const float*)d_in[0];
    const float* Wih  = (const float*)d_in[1];
    const float* Whh  = (const float*)d_in[2];
    const float* bih  = (const float*)d_in[3];
    const float* bhh  = (const float*)d_in[4];
    const float* Wout = (const float*)d_in[5];
    const float* bout = (const float*)d_in[6];
    float* out = (float*)d_out;

    cudaFuncSetAttribute(lstm_step0_kernel, cudaFuncAttributeMaxDynamicSharedMemorySize, S0_SMEM);
    cudaFuncSetAttribute(lstm_persist_kernel, cudaFuncAttributeMaxDynamicSharedMemorySize, P_SMEM);
    cudaFuncSetAttribute(proj_kernel, cudaFuncAttributeMaxDynamicSharedMemorySize, PJ_SMEM);

    pack_kernel<<<(G4 * Hdim) / 256, 256>>>(Wih, Whh, bih, bhh, Wout, x);
    lstm_step0_kernel<<<dim3(32, 4), 256, S0_SMEM>>>();
    lstm_persist_kernel<<<128, 512, P_SMEM>>>();
    proj_kernel<<<256, 512, PJ_SMEM>>>(bout, out);
}